// round 2
// baseline (speedup 1.0000x reference)
#include <cuda_runtime.h>
#include <cuda_bf16.h>
#include <math.h>

#define NN 50000
#define EE 800000
#define FIN 128
#define HC 256      // HEADS*HID = 4*64
#define HEADS 4
#define HID 64
#define C2 64       // CLASSES
#define ETOT (EE + NN)
#define NEG_ATT 0.2f
#define NEG_ACT 0.01f
#define BN_EPS 1e-5f

// ---------------- scratch (device globals; no allocation allowed) ------------
__device__ int   g_counts[NN];
__device__ int   g_incl[NN];
__device__ int   g_bsum[64];
__device__ int   g_bpref[64];
__device__ int   g_offs[NN + 1];
__device__ int   g_cursor[NN];
__device__ int   g_csr[ETOT];

__device__ float g_h1[NN * HC];      // x @ W1
__device__ float g_as1[NN * HEADS];
__device__ float g_ad1[NN * HEADS];
__device__ float g_agg1[NN * HC];    // GAT1 output (+b1)
__device__ float g_bnsum[HC];
__device__ float g_bnsq[HC];
__device__ float g_scale[HC];
__device__ float g_shift[HC];
__device__ float g_h2[NN * C2];      // hn @ W2
__device__ float g_as2[NN];
__device__ float g_ad2[NN];

// ---------------- CSR build --------------------------------------------------
__global__ void k_init() {
    int i = blockIdx.x * blockDim.x + threadIdx.x;
    if (i < NN) g_counts[i] = 1;          // self loop pre-counted
    if (i < HC) { g_bnsum[i] = 0.f; g_bnsq[i] = 0.f; }
}

__global__ void k_hist(const int* __restrict__ dst) {
    int e = blockIdx.x * blockDim.x + threadIdx.x;
    if (e < EE) atomicAdd(&g_counts[dst[e]], 1);
}

__global__ void k_scan_block() {   // grid 49, 1024 threads
    __shared__ int sd[1024];
    int t = threadIdx.x;
    int i = blockIdx.x * 1024 + t;
    int v = (i < NN) ? g_counts[i] : 0;
    sd[t] = v;
    __syncthreads();
    for (int off = 1; off < 1024; off <<= 1) {
        int add = (t >= off) ? sd[t - off] : 0;
        __syncthreads();
        sd[t] += add;
        __syncthreads();
    }
    if (i < NN) g_incl[i] = sd[t];
    if (t == 1023) g_bsum[blockIdx.x] = sd[1023];
}

__global__ void k_scan_sums(int nb) {
    if (threadIdx.x == 0 && blockIdx.x == 0) {
        int run = 0;
        for (int b = 0; b < nb; b++) { g_bpref[b] = run; run += g_bsum[b]; }
    }
}

__global__ void k_scan_finish() {
    int i = blockIdx.x * blockDim.x + threadIdx.x;
    if (i < NN) {
        int incl = g_incl[i] + g_bpref[i >> 10];
        g_offs[i + 1] = incl;
        g_cursor[i] = incl - g_counts[i];
        if (i == 0) g_offs[0] = 0;
    }
}

__global__ void k_scatter(const int* __restrict__ src, const int* __restrict__ dst) {
    int e = blockIdx.x * blockDim.x + threadIdx.x;
    if (e < EE) {
        int d = dst[e];
        int pos = atomicAdd(&g_cursor[d], 1);
        g_csr[pos] = src[e];
    }
}

__global__ void k_selfloop() {
    int n = blockIdx.x * blockDim.x + threadIdx.x;
    if (n < NN) {
        int pos = atomicAdd(&g_cursor[n], 1);
        g_csr[pos] = n;
    }
}

// ---------------- GEMM1: h1 = x @ W1  (50000x128 @ 128x256) ------------------
__global__ __launch_bounds__(256) void k_gemm1(const float* __restrict__ x,
                                               const float* __restrict__ W) {
    __shared__ float xs[32][FIN];   // 16 KB
    int t = threadIdx.x;
    int r0 = blockIdx.x * 32;
    // load 32 rows of x (float4)
    const int NV = 32 * FIN / 4;    // 1024
    float4* xs4 = (float4*)&xs[0][0];
    const float4* xg = (const float4*)x;
    for (int i = t; i < NV; i += 256) {
        int gi = r0 * (FIN / 4) + i;
        float4 v = make_float4(0.f, 0.f, 0.f, 0.f);
        if (gi < NN * (FIN / 4)) v = xg[gi];
        xs4[i] = v;
    }
    __syncthreads();
    float acc[32];
#pragma unroll
    for (int r = 0; r < 32; r++) acc[r] = 0.f;
    for (int k = 0; k < FIN; k += 4) {
        float w0 = W[(k + 0) * HC + t];
        float w1 = W[(k + 1) * HC + t];
        float w2 = W[(k + 2) * HC + t];
        float w3 = W[(k + 3) * HC + t];
#pragma unroll
        for (int r = 0; r < 32; r++) {
            float4 xv = *(const float4*)&xs[r][k];
            float a = acc[r];
            a = fmaf(xv.x, w0, a);
            a = fmaf(xv.y, w1, a);
            a = fmaf(xv.z, w2, a);
            a = fmaf(xv.w, w3, a);
            acc[r] = a;
        }
    }
#pragma unroll
    for (int r = 0; r < 32; r++) {
        int row = r0 + r;
        if (row < NN) g_h1[row * HC + t] = acc[r];
    }
}

// ---------------- alpha1: per-node dots with a_src1/a_dst1 -------------------
__global__ __launch_bounds__(256) void k_alpha1(const float* __restrict__ a_src,
                                                const float* __restrict__ a_dst) {
    int n = blockIdx.x;
    int t = threadIdx.x;
    float v = g_h1[n * HC + t];
    float ps = v * a_src[t];
    float pd = v * a_dst[t];
#pragma unroll
    for (int off = 16; off > 0; off >>= 1) {
        ps += __shfl_down_sync(0xffffffffu, ps, off);
        pd += __shfl_down_sync(0xffffffffu, pd, off);
    }
    __shared__ float ss[8], sd[8];
    int wid = t >> 5, lane = t & 31;
    if (lane == 0) { ss[wid] = ps; sd[wid] = pd; }
    __syncthreads();
    if (t < HEADS) {
        g_as1[n * HEADS + t] = ss[2 * t] + ss[2 * t + 1];
        g_ad1[n * HEADS + t] = sd[2 * t] + sd[2 * t + 1];
    }
}

// ---------------- GAT layer 1: softmax + aggregate per dst node --------------
__device__ __forceinline__ float lrelu(float v, float s) { return v > 0.f ? v : s * v; }

__global__ __launch_bounds__(256) void k_gat1(const float* __restrict__ b1) {
    int n = blockIdx.x;
    int t = threadIdx.x;
    __shared__ float4 red4[256];
    __shared__ int   s_src[256];
    __shared__ float s_alpha[256 * 4];
    __shared__ float s_ad[4], s_m[4], s_ri[4];

    int base = g_offs[n];
    int deg = g_offs[n + 1] - base;
    if (t < 4) s_ad[t] = g_ad1[n * HEADS + t];
    __syncthreads();
    float ad0 = s_ad[0], ad1 = s_ad[1], ad2 = s_ad[2], ad3 = s_ad[3];

    // pass A: max per head
    float4 lm = make_float4(-1e30f, -1e30f, -1e30f, -1e30f);
    for (int j = t; j < deg; j += 256) {
        int s = g_csr[base + j];
        float4 a = ((const float4*)g_as1)[s];
        lm.x = fmaxf(lm.x, lrelu(a.x + ad0, NEG_ATT));
        lm.y = fmaxf(lm.y, lrelu(a.y + ad1, NEG_ATT));
        lm.z = fmaxf(lm.z, lrelu(a.z + ad2, NEG_ATT));
        lm.w = fmaxf(lm.w, lrelu(a.w + ad3, NEG_ATT));
    }
    red4[t] = lm;
    __syncthreads();
    for (int off = 128; off > 0; off >>= 1) {
        if (t < off) {
            float4 o = red4[t + off], m = red4[t];
            m.x = fmaxf(m.x, o.x); m.y = fmaxf(m.y, o.y);
            m.z = fmaxf(m.z, o.z); m.w = fmaxf(m.w, o.w);
            red4[t] = m;
        }
        __syncthreads();
    }
    if (t == 0) { float4 m = red4[0]; s_m[0] = m.x; s_m[1] = m.y; s_m[2] = m.z; s_m[3] = m.w; }
    __syncthreads();
    float m0 = s_m[0], m1 = s_m[1], m2 = s_m[2], m3 = s_m[3];

    // pass B: sum of exp
    float4 ls = make_float4(0.f, 0.f, 0.f, 0.f);
    for (int j = t; j < deg; j += 256) {
        int s = g_csr[base + j];
        float4 a = ((const float4*)g_as1)[s];
        ls.x += __expf(lrelu(a.x + ad0, NEG_ATT) - m0);
        ls.y += __expf(lrelu(a.y + ad1, NEG_ATT) - m1);
        ls.z += __expf(lrelu(a.z + ad2, NEG_ATT) - m2);
        ls.w += __expf(lrelu(a.w + ad3, NEG_ATT) - m3);
    }
    red4[t] = ls;
    __syncthreads();
    for (int off = 128; off > 0; off >>= 1) {
        if (t < off) {
            float4 o = red4[t + off], m = red4[t];
            m.x += o.x; m.y += o.y; m.z += o.z; m.w += o.w;
            red4[t] = m;
        }
        __syncthreads();
    }
    if (t == 0) {
        float4 d = red4[0];
        s_ri[0] = 1.f / d.x; s_ri[1] = 1.f / d.y; s_ri[2] = 1.f / d.z; s_ri[3] = 1.f / d.w;
    }
    __syncthreads();
    float r0 = s_ri[0], r1 = s_ri[1], r2 = s_ri[2], r3 = s_ri[3];

    // pass C: aggregate per channel
    int myh = t >> 6;
    float acc = 0.f;
    for (int cb = 0; cb < deg; cb += 256) {
        int len = min(256, deg - cb);
        if (t < len) {
            int s = g_csr[base + cb + t];
            s_src[t] = s;
            float4 a = ((const float4*)g_as1)[s];
            s_alpha[t * 4 + 0] = __expf(lrelu(a.x + ad0, NEG_ATT) - m0) * r0;
            s_alpha[t * 4 + 1] = __expf(lrelu(a.y + ad1, NEG_ATT) - m1) * r1;
            s_alpha[t * 4 + 2] = __expf(lrelu(a.z + ad2, NEG_ATT) - m2) * r2;
            s_alpha[t * 4 + 3] = __expf(lrelu(a.w + ad3, NEG_ATT) - m3) * r3;
        }
        __syncthreads();
        for (int j = 0; j < len; j++) {
            acc = fmaf(s_alpha[j * 4 + myh], g_h1[s_src[j] * HC + t], acc);
        }
        __syncthreads();
    }
    g_agg1[n * HC + t] = acc + b1[t];
}

// ---------------- BatchNorm stats --------------------------------------------
__global__ __launch_bounds__(256) void k_bn_partial() {
    int t = threadIdx.x;
    int b = blockIdx.x;
    const int RPB = (NN + 255) / 256;  // 196
    int rs = b * RPB, re = min(NN, rs + RPB);
    float sum = 0.f, sq = 0.f;
    for (int r = rs; r < re; r++) {
        float v = g_agg1[r * HC + t];
        sum += v;
        sq = fmaf(v, v, sq);
    }
    atomicAdd(&g_bnsum[t], sum);
    atomicAdd(&g_bnsq[t], sq);
}

__global__ void k_bn_final(const float* __restrict__ gamma, const float* __restrict__ beta) {
    int t = threadIdx.x;
    if (t < HC) {
        float mean = g_bnsum[t] / (float)NN;
        float var = g_bnsq[t] / (float)NN - mean * mean;
        float rstd = rsqrtf(var + BN_EPS);
        float sc = gamma[t] * rstd;
        g_scale[t] = sc;
        g_shift[t] = beta[t] - mean * sc;
    }
}

// ---------------- GEMM2: h2 = leaky(BN(agg1)) @ W2  (50000x256 @ 256x64) -----
__global__ __launch_bounds__(256) void k_gemm2(const float* __restrict__ W2) {
    __shared__ float xs[32][HC];    // 32 KB
    __shared__ float s_sc[HC], s_sh[HC];
    int t = threadIdx.x;
    int c = t & 63, sub = t >> 6;
    int r0 = blockIdx.x * 32;
    for (int i = t; i < HC; i += 256) { s_sc[i] = g_scale[i]; s_sh[i] = g_shift[i]; }
    __syncthreads();
    const int NV = 32 * HC / 4;   // 2048
    float4* xs4 = (float4*)&xs[0][0];
    const float4* xg = (const float4*)g_agg1;
    for (int i = t; i < NV; i += 256) {
        int gi = r0 * (HC / 4) + i;
        float4 v = make_float4(0.f, 0.f, 0.f, 0.f);
        if (gi < NN * (HC / 4)) v = xg[gi];
        int col = (i & (HC / 4 - 1)) * 4;
        v.x = lrelu(fmaf(s_sc[col + 0], v.x, s_sh[col + 0]), NEG_ACT);
        v.y = lrelu(fmaf(s_sc[col + 1], v.y, s_sh[col + 1]), NEG_ACT);
        v.z = lrelu(fmaf(s_sc[col + 2], v.z, s_sh[col + 2]), NEG_ACT);
        v.w = lrelu(fmaf(s_sc[col + 3], v.w, s_sh[col + 3]), NEG_ACT);
        xs4[i] = v;
    }
    __syncthreads();
    float acc[8];
#pragma unroll
    for (int r = 0; r < 8; r++) acc[r] = 0.f;
    for (int k = 0; k < HC; k += 4) {
        float w0 = W2[(k + 0) * C2 + c];
        float w1 = W2[(k + 1) * C2 + c];
        float w2 = W2[(k + 2) * C2 + c];
        float w3 = W2[(k + 3) * C2 + c];
#pragma unroll
        for (int r = 0; r < 8; r++) {
            float4 xv = *(const float4*)&xs[sub * 8 + r][k];
            float a = acc[r];
            a = fmaf(xv.x, w0, a);
            a = fmaf(xv.y, w1, a);
            a = fmaf(xv.z, w2, a);
            a = fmaf(xv.w, w3, a);
            acc[r] = a;
        }
    }
#pragma unroll
    for (int r = 0; r < 8; r++) {
        int row = r0 + sub * 8 + r;
        if (row < NN) g_h2[row * C2 + c] = acc[r];
    }
}

// ---------------- alpha2 -----------------------------------------------------
__global__ __launch_bounds__(256) void k_alpha2(const float* __restrict__ a_src,
                                                const float* __restrict__ a_dst) {
    int t = threadIdx.x;
    int n = blockIdx.x * 4 + (t >> 6);
    int l64 = t & 63;
    float ps = 0.f, pd = 0.f;
    if (n < NN) {
        float v = g_h2[n * C2 + l64];
        ps = v * a_src[l64];
        pd = v * a_dst[l64];
    }
#pragma unroll
    for (int off = 16; off > 0; off >>= 1) {
        ps += __shfl_down_sync(0xffffffffu, ps, off);
        pd += __shfl_down_sync(0xffffffffu, pd, off);
    }
    __shared__ float ss[8], sd[8];
    int wid = t >> 5, lane = t & 31;
    if (lane == 0) { ss[wid] = ps; sd[wid] = pd; }
    __syncthreads();
    if (t < 4) {
        int nb = blockIdx.x * 4 + t;
        if (nb < NN) {
            g_as2[nb] = ss[2 * t] + ss[2 * t + 1];
            g_ad2[nb] = sd[2 * t] + sd[2 * t + 1];
        }
    }
}

// ---------------- GAT layer 2 → output ---------------------------------------
__global__ __launch_bounds__(64) void k_gat2(const float* __restrict__ b2,
                                             float* __restrict__ out) {
    int n = blockIdx.x;
    int t = threadIdx.x;
    __shared__ float red[64];
    __shared__ int   ssrc[64];
    __shared__ float sal[64];
    __shared__ float s_adn, s_mm, s_ri;
    int base = g_offs[n];
    int deg = g_offs[n + 1] - base;
    if (t == 0) s_adn = g_ad2[n];
    __syncthreads();
    float adn = s_adn;

    float lm = -1e30f;
    for (int j = t; j < deg; j += 64) {
        int s = g_csr[base + j];
        lm = fmaxf(lm, lrelu(g_as2[s] + adn, NEG_ATT));
    }
    red[t] = lm;
    __syncthreads();
    for (int off = 32; off > 0; off >>= 1) {
        if (t < off) red[t] = fmaxf(red[t], red[t + off]);
        __syncthreads();
    }
    if (t == 0) s_mm = red[0];
    __syncthreads();
    float mm = s_mm;

    float ls = 0.f;
    for (int j = t; j < deg; j += 64) {
        int s = g_csr[base + j];
        ls += __expf(lrelu(g_as2[s] + adn, NEG_ATT) - mm);
    }
    red[t] = ls;
    __syncthreads();
    for (int off = 32; off > 0; off >>= 1) {
        if (t < off) red[t] += red[t + off];
        __syncthreads();
    }
    if (t == 0) s_ri = 1.f / red[0];
    __syncthreads();
    float ri = s_ri;

    float acc = 0.f;
    for (int cb = 0; cb < deg; cb += 64) {
        int len = min(64, deg - cb);
        if (t < len) {
            int s = g_csr[base + cb + t];
            ssrc[t] = s;
            sal[t] = __expf(lrelu(g_as2[s] + adn, NEG_ATT) - mm) * ri;
        }
        __syncthreads();
        for (int j = 0; j < len; j++) {
            acc = fmaf(sal[j], g_h2[ssrc[j] * C2 + t], acc);
        }
        __syncthreads();
    }
    out[n * C2 + t] = acc + b2[t];
}

// ---------------- launch -----------------------------------------------------
extern "C" void kernel_launch(void* const* d_in, const int* in_sizes, int n_in,
                              void* d_out, int out_size) {
    const float* x      = (const float*)d_in[0];
    const int*   ei     = (const int*)d_in[1];
    const float* W1     = (const float*)d_in[2];
    const float* a_src1 = (const float*)d_in[3];
    const float* a_dst1 = (const float*)d_in[4];
    const float* b1     = (const float*)d_in[5];
    const float* gamma  = (const float*)d_in[6];
    const float* beta   = (const float*)d_in[7];
    const float* W2     = (const float*)d_in[8];
    const float* a_src2 = (const float*)d_in[9];
    const float* a_dst2 = (const float*)d_in[10];
    const float* b2     = (const float*)d_in[11];
    float* out = (float*)d_out;

    const int* src = ei;
    const int* dst = ei + EE;

    // CSR build
    k_init<<<(NN + 255) / 256, 256>>>();
    k_hist<<<(EE + 255) / 256, 256>>>(dst);
    const int NB = (NN + 1023) / 1024;  // 49
    k_scan_block<<<NB, 1024>>>();
    k_scan_sums<<<1, 32>>>(NB);
    k_scan_finish<<<(NN + 255) / 256, 256>>>();
    k_scatter<<<(EE + 255) / 256, 256>>>(src, dst);
    k_selfloop<<<(NN + 255) / 256, 256>>>();

    // Layer 1
    k_gemm1<<<(NN + 31) / 32, 256>>>(x, W1);
    k_alpha1<<<NN, 256>>>(a_src1, a_dst1);
    k_gat1<<<NN, 256>>>(b1);

    // BatchNorm
    k_bn_partial<<<256, 256>>>();
    k_bn_final<<<1, 256>>>(gamma, beta);

    // Layer 2
    k_gemm2<<<(NN + 31) / 32, 256>>>(W2);
    k_alpha2<<<(NN + 3) / 4, 256>>>(a_src2, a_dst2);
    k_gat2<<<NN, 64>>>(b2, out);
}

// round 4
// speedup vs baseline: 1.3845x; 1.3845x over previous
#include <cuda_runtime.h>
#include <cuda_bf16.h>
#include <math.h>
#include <stdint.h>

#define NN 50000
#define EE 800000
#define FIN 128
#define HC 256      // HEADS*HID = 4*64
#define HEADS 4
#define HID 64
#define C2 64       // CLASSES
#define ETOT (EE + NN)
#define NEG_ATT 0.2f
#define NEG_ACT 0.01f
#define BN_EPS 1e-5f

// ---------------- scratch (device globals; no allocation allowed) ------------
__device__ int   g_counts[NN];
__device__ int   g_incl[NN];
__device__ int   g_bsum[64];
__device__ int   g_bpref[64];
__device__ int   g_offs[NN + 1];
__device__ int   g_cursor[NN];
__device__ int   g_csr[ETOT];

__device__ float g_h1[NN * HC];      // x @ W1 (fp32, consumed by gather)
__device__ float g_as1[NN * HEADS];
__device__ float g_ad1[NN * HEADS];
__device__ float g_agg1[NN * HC];    // GAT1 output (+b1)
__device__ float g_bnsum[HC];
__device__ float g_bnsq[HC];
__device__ float g_scale[HC];
__device__ float g_shift[HC];
__device__ float g_h2[NN * C2];      // hn @ W2
__device__ float g_as2[NN];
__device__ float g_ad2[NN];

// bf16 split inputs for tensor-core GEMMs
__device__ __nv_bfloat16 g_xh[NN * FIN];
__device__ __nv_bfloat16 g_xl[NN * FIN];
__device__ __nv_bfloat16 g_hh[NN * HC];
__device__ __nv_bfloat16 g_hl[NN * HC];
// W fragments, fragment-linear: W1: [nhalf(2)][khalf(2)][nt(16)][kt(4)][lane(32)] uint4
__device__ uint4 g_wf1[2 * 2 * 16 * 4 * 32];   // 8192
// W2: [kq(4)][nt(8)][kt(4)][lane(32)] uint4
__device__ uint4 g_wf2[4 * 8 * 4 * 32];        // 4096

// per-node softmax stats
__device__ float g_m1[NN * 4];
__device__ float g_ri1[NN * 4];
__device__ float g_m2[NN];
__device__ float g_ri2[NN];

__device__ __forceinline__ float lrelu(float v, float s) { return v > 0.f ? v : s * v; }

__device__ __forceinline__ uint32_t pack_bf(float a, float b) {
    __nv_bfloat16 ba = __float2bfloat16(a);
    __nv_bfloat16 bb = __float2bfloat16(b);
    uint16_t ua = *(uint16_t*)&ba;
    uint16_t ub = *(uint16_t*)&bb;
    return (uint32_t)ua | ((uint32_t)ub << 16);
}

__device__ __forceinline__ void mma16816(float* c, uint32_t a0, uint32_t a1,
                                         uint32_t a2, uint32_t a3,
                                         uint32_t b0, uint32_t b1) {
    asm volatile(
        "mma.sync.aligned.m16n8k16.row.col.f32.bf16.bf16.f32 "
        "{%0,%1,%2,%3}, {%4,%5,%6,%7}, {%8,%9}, {%0,%1,%2,%3};\n"
        : "+f"(c[0]), "+f"(c[1]), "+f"(c[2]), "+f"(c[3])
        : "r"(a0), "r"(a1), "r"(a2), "r"(a3), "r"(b0), "r"(b1));
}

// ---------------- CSR build --------------------------------------------------
__global__ void k_init() {
    int i = blockIdx.x * blockDim.x + threadIdx.x;
    if (i < NN) g_counts[i] = 1;          // self loop pre-counted
    if (i < HC) { g_bnsum[i] = 0.f; g_bnsq[i] = 0.f; }
}

__global__ void k_hist(const int* __restrict__ dst) {
    int e = blockIdx.x * blockDim.x + threadIdx.x;
    if (e < EE) atomicAdd(&g_counts[dst[e]], 1);
}

__global__ void k_scan_block() {   // grid 49, 1024 threads
    __shared__ int sd[1024];
    int t = threadIdx.x;
    int i = blockIdx.x * 1024 + t;
    int v = (i < NN) ? g_counts[i] : 0;
    sd[t] = v;
    __syncthreads();
    for (int off = 1; off < 1024; off <<= 1) {
        int add = (t >= off) ? sd[t - off] : 0;
        __syncthreads();
        sd[t] += add;
        __syncthreads();
    }
    if (i < NN) g_incl[i] = sd[t];
    if (t == 1023) g_bsum[blockIdx.x] = sd[1023];
}

__global__ void k_scan_sums(int nb) {
    if (threadIdx.x == 0 && blockIdx.x == 0) {
        int run = 0;
        for (int b = 0; b < nb; b++) { g_bpref[b] = run; run += g_bsum[b]; }
    }
}

__global__ void k_scan_finish() {
    int i = blockIdx.x * blockDim.x + threadIdx.x;
    if (i < NN) {
        int incl = g_incl[i] + g_bpref[i >> 10];
        g_offs[i + 1] = incl;
        g_cursor[i] = incl - g_counts[i];
        if (i == 0) g_offs[0] = 0;
    }
}

__global__ void k_scatter(const int* __restrict__ src, const int* __restrict__ dst) {
    int e = blockIdx.x * blockDim.x + threadIdx.x;
    if (e < EE) {
        int d = dst[e];
        int pos = atomicAdd(&g_cursor[d], 1);
        g_csr[pos] = src[e];
    }
}

__global__ void k_selfloop() {
    int n = blockIdx.x * blockDim.x + threadIdx.x;
    if (n < NN) {
        int pos = atomicAdd(&g_cursor[n], 1);
        g_csr[pos] = n;
    }
}

// ---------------- bf16 split prep --------------------------------------------
__global__ void k_prep_x(const float* __restrict__ x) {
    int i = blockIdx.x * blockDim.x + threadIdx.x;
    if (i < NN * FIN) {
        float v = x[i];
        __nv_bfloat16 h = __float2bfloat16(v);
        g_xh[i] = h;
        g_xl[i] = __float2bfloat16(v - __bfloat162float(h));
    }
}

__global__ void k_prep_w1(const float* __restrict__ W) {  // W: [128][256]
    int i = blockIdx.x * blockDim.x + threadIdx.x;
    if (i >= 8192) return;
    int lane = i & 31;
    int kt = (i >> 5) & 3;
    int nt = (i >> 7) & 15;
    int kh = (i >> 11) & 1;
    int nh = (i >> 12) & 1;
    int g = lane >> 2, q = lane & 3;
    int k = kh * 64 + kt * 16 + 2 * q;
    int n = nh * 128 + nt * 8 + g;
    float w00 = W[k * HC + n];
    float w01 = W[(k + 1) * HC + n];
    float w10 = W[(k + 8) * HC + n];
    float w11 = W[(k + 9) * HC + n];
    float h00 = __bfloat162float(__float2bfloat16(w00));
    float h01 = __bfloat162float(__float2bfloat16(w01));
    float h10 = __bfloat162float(__float2bfloat16(w10));
    float h11 = __bfloat162float(__float2bfloat16(w11));
    uint32_t b0h = pack_bf(h00, h01);
    uint32_t b1h = pack_bf(h10, h11);
    uint32_t b0l = pack_bf(w00 - h00, w01 - h01);
    uint32_t b1l = pack_bf(w10 - h10, w11 - h11);
    g_wf1[i] = make_uint4(b0h, b1h, b0l, b1l);
}

__global__ void k_prep_w2(const float* __restrict__ W) {  // W: [256][64]
    int i = blockIdx.x * blockDim.x + threadIdx.x;
    if (i >= 4096) return;
    int lane = i & 31;
    int kt = (i >> 5) & 3;
    int nt = (i >> 7) & 7;
    int kq = (i >> 10) & 3;
    int g = lane >> 2, q = lane & 3;
    int k = kq * 64 + kt * 16 + 2 * q;
    int n = nt * 8 + g;
    float w00 = W[k * C2 + n];
    float w01 = W[(k + 1) * C2 + n];
    float w10 = W[(k + 8) * C2 + n];
    float w11 = W[(k + 9) * C2 + n];
    float h00 = __bfloat162float(__float2bfloat16(w00));
    float h01 = __bfloat162float(__float2bfloat16(w01));
    float h10 = __bfloat162float(__float2bfloat16(w10));
    float h11 = __bfloat162float(__float2bfloat16(w11));
    g_wf2[i] = make_uint4(pack_bf(h00, h01), pack_bf(h10, h11),
                          pack_bf(w00 - h00, w01 - h01), pack_bf(w10 - h10, w11 - h11));
}

// ---------------- GEMM1: h1 = x @ W1 via bf16-split tensor MMA ---------------
// grid (391, 2), 256 threads. Warp w: rows [bx*128 + w*16, +16), cols nh*128..+128
__global__ __launch_bounds__(256) void k_gemm1() {
    __shared__ uint4 bs[16][4][32];    // 32 KB: [nt][kt][lane]
    int t = threadIdx.x;
    int w = t >> 5, lane = t & 31;
    int g = lane >> 2, q = lane & 3;
    int m0 = blockIdx.x * 128 + w * 16 + g;
    int m1 = m0 + 8;
    bool v0 = m0 < NN, v1 = m1 < NN;
    int nh = blockIdx.y;

    float acc[16][4];
#pragma unroll
    for (int nt = 0; nt < 16; nt++)
#pragma unroll
        for (int r = 0; r < 4; r++) acc[nt][r] = 0.f;

    for (int kh = 0; kh < 2; kh++) {
        const uint4* srcw = g_wf1 + (nh * 2 + kh) * 2048;
        for (int i = t; i < 2048; i += 256) ((uint4*)bs)[i] = srcw[i];
        __syncthreads();
#pragma unroll
        for (int kt = 0; kt < 4; kt++) {
            int kk = kh * 64 + kt * 16 + 2 * q;
            uint32_t ah0 = 0, ah1 = 0, ah2 = 0, ah3 = 0;
            uint32_t al0 = 0, al1 = 0, al2 = 0, al3 = 0;
            if (v0) {
                ah0 = *(const uint32_t*)&g_xh[m0 * FIN + kk];
                ah2 = *(const uint32_t*)&g_xh[m0 * FIN + kk + 8];
                al0 = *(const uint32_t*)&g_xl[m0 * FIN + kk];
                al2 = *(const uint32_t*)&g_xl[m0 * FIN + kk + 8];
            }
            if (v1) {
                ah1 = *(const uint32_t*)&g_xh[m1 * FIN + kk];
                ah3 = *(const uint32_t*)&g_xh[m1 * FIN + kk + 8];
                al1 = *(const uint32_t*)&g_xl[m1 * FIN + kk];
                al3 = *(const uint32_t*)&g_xl[m1 * FIN + kk + 8];
            }
#pragma unroll
            for (int nt = 0; nt < 16; nt++) {
                uint4 b = bs[nt][kt][lane];
                mma16816(acc[nt], ah0, ah1, ah2, ah3, b.x, b.y);  // hi*hi
                mma16816(acc[nt], ah0, ah1, ah2, ah3, b.z, b.w);  // hi*lo
                mma16816(acc[nt], al0, al1, al2, al3, b.x, b.y);  // lo*hi
            }
        }
        __syncthreads();
    }
    int nbase = nh * 128;
#pragma unroll
    for (int nt = 0; nt < 16; nt++) {
        int col = nbase + nt * 8 + 2 * q;
        if (v0) *(float2*)&g_h1[m0 * HC + col] = make_float2(acc[nt][0], acc[nt][1]);
        if (v1) *(float2*)&g_h1[m1 * HC + col] = make_float2(acc[nt][2], acc[nt][3]);
    }
}

// ---------------- alpha1 -----------------------------------------------------
__global__ __launch_bounds__(256) void k_alpha1(const float* __restrict__ a_src,
                                                const float* __restrict__ a_dst) {
    int n = blockIdx.x;
    int t = threadIdx.x;
    float v = g_h1[n * HC + t];
    float ps = v * a_src[t];
    float pd = v * a_dst[t];
#pragma unroll
    for (int off = 16; off > 0; off >>= 1) {
        ps += __shfl_down_sync(0xffffffffu, ps, off);
        pd += __shfl_down_sync(0xffffffffu, pd, off);
    }
    __shared__ float ss[8], sd[8];
    int wid = t >> 5, lane = t & 31;
    if (lane == 0) { ss[wid] = ps; sd[wid] = pd; }
    __syncthreads();
    if (t < HEADS) {
        g_as1[n * HEADS + t] = ss[2 * t] + ss[2 * t + 1];
        g_ad1[n * HEADS + t] = sd[2 * t] + sd[2 * t + 1];
    }
}

// ---------------- softmax stats layer 1: warp per node -----------------------
__global__ __launch_bounds__(256) void k_soft1() {
    int w = threadIdx.x >> 5, lane = threadIdx.x & 31;
    int n = blockIdx.x * 8 + w;
    if (n >= NN) return;
    int base = g_offs[n], deg = g_offs[n + 1] - base;
    float4 ad = ((const float4*)g_ad1)[n];
    float4 mx = make_float4(-1e30f, -1e30f, -1e30f, -1e30f);
    for (int j = lane; j < deg; j += 32) {
        int s = g_csr[base + j];
        float4 a = ((const float4*)g_as1)[s];
        mx.x = fmaxf(mx.x, lrelu(a.x + ad.x, NEG_ATT));
        mx.y = fmaxf(mx.y, lrelu(a.y + ad.y, NEG_ATT));
        mx.z = fmaxf(mx.z, lrelu(a.z + ad.z, NEG_ATT));
        mx.w = fmaxf(mx.w, lrelu(a.w + ad.w, NEG_ATT));
    }
#pragma unroll
    for (int off = 16; off > 0; off >>= 1) {
        mx.x = fmaxf(mx.x, __shfl_xor_sync(0xffffffffu, mx.x, off));
        mx.y = fmaxf(mx.y, __shfl_xor_sync(0xffffffffu, mx.y, off));
        mx.z = fmaxf(mx.z, __shfl_xor_sync(0xffffffffu, mx.z, off));
        mx.w = fmaxf(mx.w, __shfl_xor_sync(0xffffffffu, mx.w, off));
    }
    float4 sm = make_float4(0.f, 0.f, 0.f, 0.f);
    for (int j = lane; j < deg; j += 32) {
        int s = g_csr[base + j];
        float4 a = ((const float4*)g_as1)[s];
        sm.x += __expf(lrelu(a.x + ad.x, NEG_ATT) - mx.x);
        sm.y += __expf(lrelu(a.y + ad.y, NEG_ATT) - mx.y);
        sm.z += __expf(lrelu(a.z + ad.z, NEG_ATT) - mx.z);
        sm.w += __expf(lrelu(a.w + ad.w, NEG_ATT) - mx.w);
    }
#pragma unroll
    for (int off = 16; off > 0; off >>= 1) {
        sm.x += __shfl_xor_sync(0xffffffffu, sm.x, off);
        sm.y += __shfl_xor_sync(0xffffffffu, sm.y, off);
        sm.z += __shfl_xor_sync(0xffffffffu, sm.z, off);
        sm.w += __shfl_xor_sync(0xffffffffu, sm.w, off);
    }
    if (lane == 0) {
        ((float4*)g_m1)[n] = mx;
        ((float4*)g_ri1)[n] = make_float4(1.f / sm.x, 1.f / sm.y, 1.f / sm.z, 1.f / sm.w);
    }
}

// ---------------- GAT layer 1 aggregation ------------------------------------
__global__ __launch_bounds__(256) void k_gat1(const float* __restrict__ b1) {
    int n = blockIdx.x;
    int t = threadIdx.x;
    __shared__ int s_src[256];
    __shared__ float s_alpha[256 * 4];
    __shared__ float4 s_adv, s_mv, s_rv;
    if (t == 0) {
        s_adv = ((const float4*)g_ad1)[n];
        s_mv = ((const float4*)g_m1)[n];
        s_rv = ((const float4*)g_ri1)[n];
    }
    __syncthreads();
    float4 ad = s_adv, m = s_mv, ri = s_rv;
    int base = g_offs[n], deg = g_offs[n + 1] - base;
    int myh = t >> 6;
    float acc = 0.f;
    for (int cb = 0; cb < deg; cb += 256) {
        int len = min(256, deg - cb);
        if (t < len) {
            int s = g_csr[base + cb + t];
            s_src[t] = s;
            float4 a = ((const float4*)g_as1)[s];
            s_alpha[t * 4 + 0] = __expf(lrelu(a.x + ad.x, NEG_ATT) - m.x) * ri.x;
            s_alpha[t * 4 + 1] = __expf(lrelu(a.y + ad.y, NEG_ATT) - m.y) * ri.y;
            s_alpha[t * 4 + 2] = __expf(lrelu(a.z + ad.z, NEG_ATT) - m.z) * ri.z;
            s_alpha[t * 4 + 3] = __expf(lrelu(a.w + ad.w, NEG_ATT) - m.w) * ri.w;
        }
        __syncthreads();
        int j = 0;
        for (; j + 4 <= len; j += 4) {
            int r0 = s_src[j], r1 = s_src[j + 1], r2 = s_src[j + 2], r3 = s_src[j + 3];
            float a0 = s_alpha[(j + 0) * 4 + myh];
            float a1 = s_alpha[(j + 1) * 4 + myh];
            float a2 = s_alpha[(j + 2) * 4 + myh];
            float a3 = s_alpha[(j + 3) * 4 + myh];
            float v0 = g_h1[r0 * HC + t];
            float v1 = g_h1[r1 * HC + t];
            float v2 = g_h1[r2 * HC + t];
            float v3 = g_h1[r3 * HC + t];
            acc = fmaf(a0, v0, acc);
            acc = fmaf(a1, v1, acc);
            acc = fmaf(a2, v2, acc);
            acc = fmaf(a3, v3, acc);
        }
        for (; j < len; j++)
            acc = fmaf(s_alpha[j * 4 + myh], g_h1[s_src[j] * HC + t], acc);
        __syncthreads();
    }
    g_agg1[n * HC + t] = acc + b1[t];
}

// ---------------- BatchNorm stats --------------------------------------------
__global__ __launch_bounds__(256) void k_bn_partial() {
    int t = threadIdx.x;
    int b = blockIdx.x;
    const int RPB = (NN + 255) / 256;  // 196
    int rs = b * RPB, re = min(NN, rs + RPB);
    float sum = 0.f, sq = 0.f;
    for (int r = rs; r < re; r++) {
        float v = g_agg1[r * HC + t];
        sum += v;
        sq = fmaf(v, v, sq);
    }
    atomicAdd(&g_bnsum[t], sum);
    atomicAdd(&g_bnsq[t], sq);
}

__global__ void k_bn_final(const float* __restrict__ gamma, const float* __restrict__ beta) {
    int t = threadIdx.x;
    if (t < HC) {
        float mean = g_bnsum[t] / (float)NN;
        float var = g_bnsq[t] / (float)NN - mean * mean;
        float rstd = rsqrtf(var + BN_EPS);
        float sc = gamma[t] * rstd;
        g_scale[t] = sc;
        g_shift[t] = beta[t] - mean * sc;
    }
}

// ---------------- prep layer-2 input: BN + leaky + bf16 split ----------------
__global__ void k_prep_h() {
    int i = blockIdx.x * blockDim.x + threadIdx.x;
    if (i < NN * HC) {
        int c = i & (HC - 1);
        float v = g_agg1[i];
        v = lrelu(fmaf(g_scale[c], v, g_shift[c]), NEG_ACT);
        __nv_bfloat16 h = __float2bfloat16(v);
        g_hh[i] = h;
        g_hl[i] = __float2bfloat16(v - __bfloat162float(h));
    }
}

// ---------------- GEMM2: h2 = hn @ W2 via bf16-split tensor MMA --------------
// grid 391, 256 threads. Warp w: rows [bx*128 + w*16, +16), all 64 cols.
__global__ __launch_bounds__(256) void k_gemm2() {
    __shared__ uint4 bs[8][4][32];     // 16 KB: [nt][kt][lane]
    int t = threadIdx.x;
    int w = t >> 5, lane = t & 31;
    int g = lane >> 2, q = lane & 3;
    int m0 = blockIdx.x * 128 + w * 16 + g;
    int m1 = m0 + 8;
    bool v0 = m0 < NN, v1 = m1 < NN;

    float acc[8][4];
#pragma unroll
    for (int nt = 0; nt < 8; nt++)
#pragma unroll
        for (int r = 0; r < 4; r++) acc[nt][r] = 0.f;

    for (int kq = 0; kq < 4; kq++) {
        const uint4* srcw = g_wf2 + kq * 1024;
        for (int i = t; i < 1024; i += 256) ((uint4*)bs)[i] = srcw[i];
        __syncthreads();
#pragma unroll
        for (int kt = 0; kt < 4; kt++) {
            int kk = kq * 64 + kt * 16 + 2 * q;
            uint32_t ah0 = 0, ah1 = 0, ah2 = 0, ah3 = 0;
            uint32_t al0 = 0, al1 = 0, al2 = 0, al3 = 0;
            if (v0) {
                ah0 = *(const uint32_t*)&g_hh[m0 * HC + kk];
                ah2 = *(const uint32_t*)&g_hh[m0 * HC + kk + 8];
                al0 = *(const uint32_t*)&g_hl[m0 * HC + kk];
                al2 = *(const uint32_t*)&g_hl[m0 * HC + kk + 8];
            }
            if (v1) {
                ah1 = *(const uint32_t*)&g_hh[m1 * HC + kk];
                ah3 = *(const uint32_t*)&g_hh[m1 * HC + kk + 8];
                al1 = *(const uint32_t*)&g_hl[m1 * HC + kk];
                al3 = *(const uint32_t*)&g_hl[m1 * HC + kk + 8];
            }
#pragma unroll
            for (int nt = 0; nt < 8; nt++) {
                uint4 b = bs[nt][kt][lane];
                mma16816(acc[nt], ah0, ah1, ah2, ah3, b.x, b.y);
                mma16816(acc[nt], ah0, ah1, ah2, ah3, b.z, b.w);
                mma16816(acc[nt], al0, al1, al2, al3, b.x, b.y);
            }
        }
        __syncthreads();
    }
#pragma unroll
    for (int nt = 0; nt < 8; nt++) {
        int col = nt * 8 + 2 * q;
        if (v0) *(float2*)&g_h2[m0 * C2 + col] = make_float2(acc[nt][0], acc[nt][1]);
        if (v1) *(float2*)&g_h2[m1 * C2 + col] = make_float2(acc[nt][2], acc[nt][3]);
    }
}

// ---------------- alpha2 -----------------------------------------------------
__global__ __launch_bounds__(256) void k_alpha2(const float* __restrict__ a_src,
                                                const float* __restrict__ a_dst) {
    int t = threadIdx.x;
    int n = blockIdx.x * 4 + (t >> 6);
    int l64 = t & 63;
    float ps = 0.f, pd = 0.f;
    if (n < NN) {
        float v = g_h2[n * C2 + l64];
        ps = v * a_src[l64];
        pd = v * a_dst[l64];
    }
#pragma unroll
    for (int off = 16; off > 0; off >>= 1) {
        ps += __shfl_down_sync(0xffffffffu, ps, off);
        pd += __shfl_down_sync(0xffffffffu, pd, off);
    }
    __shared__ float ss[8], sd[8];
    int wid = t >> 5, lane = t & 31;
    if (lane == 0) { ss[wid] = ps; sd[wid] = pd; }
    __syncthreads();
    if (t < 4) {
        int nb = blockIdx.x * 4 + t;
        if (nb < NN) {
            g_as2[nb] = ss[2 * t] + ss[2 * t + 1];
            g_ad2[nb] = sd[2 * t] + sd[2 * t + 1];
        }
    }
}

// ---------------- softmax stats layer 2: warp per node -----------------------
__global__ __launch_bounds__(256) void k_soft2() {
    int w = threadIdx.x >> 5, lane = threadIdx.x & 31;
    int n = blockIdx.x * 8 + w;
    if (n >= NN) return;
    int base = g_offs[n], deg = g_offs[n + 1] - base;
    float ad = g_ad2[n];
    float mx = -1e30f;
    for (int j = lane; j < deg; j += 32) {
        int s = g_csr[base + j];
        mx = fmaxf(mx, lrelu(g_as2[s] + ad, NEG_ATT));
    }
#pragma unroll
    for (int off = 16; off > 0; off >>= 1)
        mx = fmaxf(mx, __shfl_xor_sync(0xffffffffu, mx, off));
    float sm = 0.f;
    for (int j = lane; j < deg; j += 32) {
        int s = g_csr[base + j];
        sm += __expf(lrelu(g_as2[s] + ad, NEG_ATT) - mx);
    }
#pragma unroll
    for (int off = 16; off > 0; off >>= 1)
        sm += __shfl_xor_sync(0xffffffffu, sm, off);
    if (lane == 0) { g_m2[n] = mx; g_ri2[n] = 1.f / sm; }
}

// ---------------- GAT layer 2 → output ---------------------------------------
__global__ __launch_bounds__(64) void k_gat2(const float* __restrict__ b2,
                                             float* __restrict__ out) {
    int n = blockIdx.x;
    int t = threadIdx.x;
    __shared__ int ssrc[64];
    __shared__ float sal[64];
    __shared__ float s_adn, s_mm, s_ri;
    int base = g_offs[n];
    int deg = g_offs[n + 1] - base;
    if (t == 0) { s_adn = g_ad2[n]; s_mm = g_m2[n]; s_ri = g_ri2[n]; }
    __syncthreads();
    float adn = s_adn, mm = s_mm, ri = s_ri;

    float acc = 0.f;
    for (int cb = 0; cb < deg; cb += 64) {
        int len = min(64, deg - cb);
        if (t < len) {
            int s = g_csr[base + cb + t];
            ssrc[t] = s;
            sal[t] = __expf(lrelu(g_as2[s] + adn, NEG_ATT) - mm) * ri;
        }
        __syncthreads();
        int j = 0;
        for (; j + 4 <= len; j += 4) {
            int r0 = ssrc[j], r1 = ssrc[j + 1], r2 = ssrc[j + 2], r3 = ssrc[j + 3];
            float a0 = sal[j], a1 = sal[j + 1], a2 = sal[j + 2], a3 = sal[j + 3];
            float v0 = g_h2[r0 * C2 + t];
            float v1 = g_h2[r1 * C2 + t];
            float v2 = g_h2[r2 * C2 + t];
            float v3 = g_h2[r3 * C2 + t];
            acc = fmaf(a0, v0, acc);
            acc = fmaf(a1, v1, acc);
            acc = fmaf(a2, v2, acc);
            acc = fmaf(a3, v3, acc);
        }
        for (; j < len; j++)
            acc = fmaf(sal[j], g_h2[ssrc[j] * C2 + t], acc);
        __syncthreads();
    }
    out[n * C2 + t] = acc + b2[t];
}

// ---------------- launch -----------------------------------------------------
extern "C" void kernel_launch(void* const* d_in, const int* in_sizes, int n_in,
                              void* d_out, int out_size) {
    const float* x      = (const float*)d_in[0];
    const int*   ei     = (const int*)d_in[1];
    const float* W1     = (const float*)d_in[2];
    const float* a_src1 = (const float*)d_in[3];
    const float* a_dst1 = (const float*)d_in[4];
    const float* b1     = (const float*)d_in[5];
    const float* gamma  = (const float*)d_in[6];
    const float* beta   = (const float*)d_in[7];
    const float* W2     = (const float*)d_in[8];
    const float* a_src2 = (const float*)d_in[9];
    const float* a_dst2 = (const float*)d_in[10];
    const float* b2     = (const float*)d_in[11];
    float* out = (float*)d_out;

    const int* src = ei;
    const int* dst = ei + EE;

    // CSR build
    k_init<<<(NN + 255) / 256, 256>>>();
    k_hist<<<(EE + 255) / 256, 256>>>(dst);
    const int NB = (NN + 1023) / 1024;  // 49
    k_scan_block<<<NB, 1024>>>();
    k_scan_sums<<<1, 32>>>(NB);
    k_scan_finish<<<(NN + 255) / 256, 256>>>();
    k_scatter<<<(EE + 255) / 256, 256>>>(src, dst);
    k_selfloop<<<(NN + 255) / 256, 256>>>();

    // bf16-split prep (x, W1, W2)
    k_prep_x<<<(NN * FIN + 255) / 256, 256>>>(x);
    k_prep_w1<<<32, 256>>>(W1);
    k_prep_w2<<<16, 256>>>(W2);

    // Layer 1
    k_gemm1<<<dim3((NN + 127) / 128, 2), 256>>>();
    k_alpha1<<<NN, 256>>>(a_src1, a_dst1);
    k_soft1<<<(NN + 7) / 8, 256>>>();
    k_gat1<<<NN, 256>>>(b1);

    // BatchNorm + layer-2 input prep
    k_bn_partial<<<256, 256>>>();
    k_bn_final<<<1, 256>>>(gamma, beta);
    k_prep_h<<<(NN * HC + 255) / 256, 256>>>();

    // Layer 2
    k_gemm2<<<(NN + 127) / 128, 256>>>();
    k_alpha2<<<(NN + 3) / 4, 256>>>(a_src2, a_dst2);
    k_soft2<<<(NN + 7) / 8, 256>>>();
    k_gat2<<<NN, 64>>>(b2, out);
}

// round 7
// speedup vs baseline: 1.7691x; 1.2778x over previous
#include <cuda_runtime.h>
#include <cuda_bf16.h>
#include <math.h>
#include <stdint.h>

#define NN 50000
#define EE 800000
#define FIN 128
#define HC 256      // HEADS*HID = 4*64
#define HEADS 4
#define HID 64
#define C2 64       // CLASSES
#define ETOT (EE + NN)
#define NEG_ATT 0.2f
#define NEG_ACT 0.01f
#define BN_EPS 1e-5f

// ---------------- scratch (device globals; no allocation allowed) ------------
__device__ int   g_counts[NN];
__device__ int   g_incl[NN];
__device__ int   g_bsum[64];
__device__ int   g_offs[NN + 1];
__device__ int   g_cursor[NN];
__device__ int   g_csr[ETOT];

__device__ float g_h1[NN * HC];      // x @ W1 (fp32, consumed by gather)
__device__ float g_as1[NN * HEADS];
__device__ float g_ad1[NN * HEADS];
__device__ float g_agg1[NN * HC];    // GAT1 output (+b1)
__device__ float g_bnsum[HC];
__device__ float g_bnsq[HC];
__device__ float g_scale[HC];
__device__ float g_shift[HC];
__device__ float g_h2[NN * C2];      // hn @ W2
__device__ float g_as2[NN];
__device__ float g_ad2[NN];

// W fragments, fragment-linear: W1: [nhalf(2)][khalf(2)][nt(16)][kt(4)][lane(32)] uint4
__device__ uint4 g_wf1[2 * 2 * 16 * 4 * 32];   // 8192
// W2: [kq(4)][nt(8)][kt(4)][lane(32)] uint4
__device__ uint4 g_wf2[4 * 8 * 4 * 32];        // 4096

// per-edge normalized attention weights
__device__ float g_alE1[ETOT * 4];   // 13.6 MB
__device__ float g_alE2[ETOT];

__device__ __forceinline__ float lrelu(float v, float s) { return v > 0.f ? v : s * v; }

__device__ __forceinline__ uint32_t pack_bf(float a, float b) {
    __nv_bfloat16 ba = __float2bfloat16(a);
    __nv_bfloat16 bb = __float2bfloat16(b);
    uint16_t ua = *(uint16_t*)&ba;
    uint16_t ub = *(uint16_t*)&bb;
    return (uint32_t)ua | ((uint32_t)ub << 16);
}

// split a float2 into bf16 hi pair + bf16 lo-residual pair
__device__ __forceinline__ void split2(float2 u, uint32_t& hi, uint32_t& lo) {
    float hx = __bfloat162float(__float2bfloat16(u.x));
    float hy = __bfloat162float(__float2bfloat16(u.y));
    hi = pack_bf(hx, hy);
    lo = pack_bf(u.x - hx, u.y - hy);
}

__device__ __forceinline__ void mma16816(float* c, uint32_t a0, uint32_t a1,
                                         uint32_t a2, uint32_t a3,
                                         uint32_t b0, uint32_t b1) {
    asm volatile(
        "mma.sync.aligned.m16n8k16.row.col.f32.bf16.bf16.f32 "
        "{%0,%1,%2,%3}, {%4,%5,%6,%7}, {%8,%9}, {%0,%1,%2,%3};\n"
        : "+f"(c[0]), "+f"(c[1]), "+f"(c[2]), "+f"(c[3])
        : "r"(a0), "r"(a1), "r"(a2), "r"(a3), "r"(b0), "r"(b1));
}

// ---------------- CSR build --------------------------------------------------
__global__ void k_init() {
    int i = blockIdx.x * blockDim.x + threadIdx.x;
    if (i < NN) g_counts[i] = 1;          // self loop pre-counted
    if (i < HC) { g_bnsum[i] = 0.f; g_bnsq[i] = 0.f; }
}

__global__ void k_hist(const int* __restrict__ dst) {
    int e = blockIdx.x * blockDim.x + threadIdx.x;
    if (e < EE) atomicAdd(&g_counts[dst[e]], 1);
}

__global__ void k_scan_block() {   // grid 49, 1024 threads
    __shared__ int sd[1024];
    int t = threadIdx.x;
    int i = blockIdx.x * 1024 + t;
    int v = (i < NN) ? g_counts[i] : 0;
    sd[t] = v;
    __syncthreads();
    for (int off = 1; off < 1024; off <<= 1) {
        int add = (t >= off) ? sd[t - off] : 0;
        __syncthreads();
        sd[t] += add;
        __syncthreads();
    }
    if (i < NN) g_incl[i] = sd[t];
    if (t == 1023) g_bsum[blockIdx.x] = sd[1023];
}

// finish scan, insert self-loop at slot 0 of each node, set cursor
__global__ void k_scan_finish() {
    __shared__ int s_pref;
    int b = blockIdx.x;
    int t = threadIdx.x;
    int i = b * 256 + t;
    if (t == 0) {
        int chunk = b >> 2;        // all 256 indices share i>>10
        int run = 0;
        for (int c = 0; c < chunk; c++) run += g_bsum[c];
        s_pref = run;
    }
    __syncthreads();
    if (i < NN) {
        int incl = g_incl[i] + s_pref;
        g_offs[i + 1] = incl;
        int start = incl - g_counts[i];
        g_csr[start] = i;          // self loop occupies first slot
        g_cursor[i] = start + 1;
        if (i == 0) g_offs[0] = 0;
    }
}

__global__ void k_scatter(const int* __restrict__ src, const int* __restrict__ dst) {
    int e = blockIdx.x * blockDim.x + threadIdx.x;
    if (e < EE) {
        int d = dst[e];
        int pos = atomicAdd(&g_cursor[d], 1);
        g_csr[pos] = src[e];
    }
}

// ---------------- W fragment prep --------------------------------------------
__global__ void k_prep_w1(const float* __restrict__ W) {  // W: [128][256]
    int i = blockIdx.x * blockDim.x + threadIdx.x;
    if (i >= 8192) return;
    int lane = i & 31;
    int kt = (i >> 5) & 3;
    int nt = (i >> 7) & 15;
    int kh = (i >> 11) & 1;
    int nh = (i >> 12) & 1;
    int g = lane >> 2, q = lane & 3;
    int k = kh * 64 + kt * 16 + 2 * q;
    int n = nh * 128 + nt * 8 + g;
    float w00 = W[k * HC + n];
    float w01 = W[(k + 1) * HC + n];
    float w10 = W[(k + 8) * HC + n];
    float w11 = W[(k + 9) * HC + n];
    float h00 = __bfloat162float(__float2bfloat16(w00));
    float h01 = __bfloat162float(__float2bfloat16(w01));
    float h10 = __bfloat162float(__float2bfloat16(w10));
    float h11 = __bfloat162float(__float2bfloat16(w11));
    g_wf1[i] = make_uint4(pack_bf(h00, h01), pack_bf(h10, h11),
                          pack_bf(w00 - h00, w01 - h01), pack_bf(w10 - h10, w11 - h11));
}

__global__ void k_prep_w2(const float* __restrict__ W) {  // W: [256][64]
    int i = blockIdx.x * blockDim.x + threadIdx.x;
    if (i >= 4096) return;
    int lane = i & 31;
    int kt = (i >> 5) & 3;
    int nt = (i >> 7) & 7;
    int kq = (i >> 10) & 3;
    int g = lane >> 2, q = lane & 3;
    int k = kq * 64 + kt * 16 + 2 * q;
    int n = nt * 8 + g;
    float w00 = W[k * C2 + n];
    float w01 = W[(k + 1) * C2 + n];
    float w10 = W[(k + 8) * C2 + n];
    float w11 = W[(k + 9) * C2 + n];
    float h00 = __bfloat162float(__float2bfloat16(w00));
    float h01 = __bfloat162float(__float2bfloat16(w01));
    float h10 = __bfloat162float(__float2bfloat16(w10));
    float h11 = __bfloat162float(__float2bfloat16(w11));
    g_wf2[i] = make_uint4(pack_bf(h00, h01), pack_bf(h10, h11),
                          pack_bf(w00 - h00, w01 - h01), pack_bf(w10 - h10, w11 - h11));
}

// ---------------- GEMM1: h1 = x @ W1, fused bf16-split + alpha1 epilogue -----
// grid (391, 2), 256 threads. Warp w: rows [bx*128+w*16, +16), cols nh*128..+128
__global__ __launch_bounds__(256) void k_gemm1(const float* __restrict__ x,
                                               const float* __restrict__ a_src,
                                               const float* __restrict__ a_dst) {
    __shared__ uint4 bs[16][4][32];    // 32 KB
    int t = threadIdx.x;
    int w = t >> 5, lane = t & 31;
    int g = lane >> 2, q = lane & 3;
    int m0 = blockIdx.x * 128 + w * 16 + g;
    int m1 = m0 + 8;
    bool v0 = m0 < NN, v1 = m1 < NN;
    int nh = blockIdx.y;

    float acc[16][4];
#pragma unroll
    for (int nt = 0; nt < 16; nt++)
#pragma unroll
        for (int r = 0; r < 4; r++) acc[nt][r] = 0.f;

    for (int kh = 0; kh < 2; kh++) {
        const uint4* srcw = g_wf1 + (nh * 2 + kh) * 2048;
        for (int i = t; i < 2048; i += 256) ((uint4*)bs)[i] = srcw[i];
        __syncthreads();
#pragma unroll
        for (int kt = 0; kt < 4; kt++) {
            int kk = kh * 64 + kt * 16 + 2 * q;
            uint32_t ah0 = 0, ah1 = 0, ah2 = 0, ah3 = 0;
            uint32_t al0 = 0, al1 = 0, al2 = 0, al3 = 0;
            if (v0) {
                split2(*(const float2*)&x[m0 * FIN + kk], ah0, al0);
                split2(*(const float2*)&x[m0 * FIN + kk + 8], ah2, al2);
            }
            if (v1) {
                split2(*(const float2*)&x[m1 * FIN + kk], ah1, al1);
                split2(*(const float2*)&x[m1 * FIN + kk + 8], ah3, al3);
            }
#pragma unroll
            for (int nt = 0; nt < 16; nt++) {
                uint4 b = bs[nt][kt][lane];
                mma16816(acc[nt], ah0, ah1, ah2, ah3, b.x, b.y);  // hi*hi
                mma16816(acc[nt], ah0, ah1, ah2, ah3, b.z, b.w);  // hi*lo
                mma16816(acc[nt], al0, al1, al2, al3, b.x, b.y);  // lo*hi
            }
        }
        __syncthreads();
    }
    int nbase = nh * 128;
#pragma unroll
    for (int nt = 0; nt < 16; nt++) {
        int col = nbase + nt * 8 + 2 * q;
        if (v0) *(float2*)&g_h1[m0 * HC + col] = make_float2(acc[nt][0], acc[nt][1]);
        if (v1) *(float2*)&g_h1[m1 * HC + col] = make_float2(acc[nt][2], acc[nt][3]);
    }

    // fused alpha: per-head dot with a_src / a_dst (heads align with nt groups)
    float ps[2][2] = {{0.f, 0.f}, {0.f, 0.f}};
    float pd[2][2] = {{0.f, 0.f}, {0.f, 0.f}};
#pragma unroll
    for (int nt = 0; nt < 16; nt++) {
        int hl = nt >> 3;
        int c0 = nbase + nt * 8 + 2 * q;
        float s0 = a_src[c0], s1 = a_src[c0 + 1];
        float d0 = a_dst[c0], d1 = a_dst[c0 + 1];
        ps[hl][0] += acc[nt][0] * s0 + acc[nt][1] * s1;
        pd[hl][0] += acc[nt][0] * d0 + acc[nt][1] * d1;
        ps[hl][1] += acc[nt][2] * s0 + acc[nt][3] * s1;
        pd[hl][1] += acc[nt][2] * d0 + acc[nt][3] * d1;
    }
#pragma unroll
    for (int off = 1; off <= 2; off <<= 1) {
#pragma unroll
        for (int hl = 0; hl < 2; hl++) {
            ps[hl][0] += __shfl_xor_sync(0xffffffffu, ps[hl][0], off);
            ps[hl][1] += __shfl_xor_sync(0xffffffffu, ps[hl][1], off);
            pd[hl][0] += __shfl_xor_sync(0xffffffffu, pd[hl][0], off);
            pd[hl][1] += __shfl_xor_sync(0xffffffffu, pd[hl][1], off);
        }
    }
    if (q == 0) {
#pragma unroll
        for (int hl = 0; hl < 2; hl++) {
            int gh = nh * 2 + hl;
            if (v0) { g_as1[m0 * 4 + gh] = ps[hl][0]; g_ad1[m0 * 4 + gh] = pd[hl][0]; }
            if (v1) { g_as1[m1 * 4 + gh] = ps[hl][1]; g_ad1[m1 * 4 + gh] = pd[hl][1]; }
        }
    }
}

// ---------------- softmax stats layer 1: warp per node, writes edge alphas ---
__global__ __launch_bounds__(256) void k_soft1() {
    int w = threadIdx.x >> 5, lane = threadIdx.x & 31;
    int n = blockIdx.x * 8 + w;
    if (n >= NN) return;
    int base = g_offs[n], deg = g_offs[n + 1] - base;
    float4 ad = ((const float4*)g_ad1)[n];
    float4 mx = make_float4(-1e30f, -1e30f, -1e30f, -1e30f);
    for (int j = lane; j < deg; j += 32) {
        int s = g_csr[base + j];
        float4 a = ((const float4*)g_as1)[s];
        mx.x = fmaxf(mx.x, lrelu(a.x + ad.x, NEG_ATT));
        mx.y = fmaxf(mx.y, lrelu(a.y + ad.y, NEG_ATT));
        mx.z = fmaxf(mx.z, lrelu(a.z + ad.z, NEG_ATT));
        mx.w = fmaxf(mx.w, lrelu(a.w + ad.w, NEG_ATT));
    }
#pragma unroll
    for (int off = 16; off > 0; off >>= 1) {
        mx.x = fmaxf(mx.x, __shfl_xor_sync(0xffffffffu, mx.x, off));
        mx.y = fmaxf(mx.y, __shfl_xor_sync(0xffffffffu, mx.y, off));
        mx.z = fmaxf(mx.z, __shfl_xor_sync(0xffffffffu, mx.z, off));
        mx.w = fmaxf(mx.w, __shfl_xor_sync(0xffffffffu, mx.w, off));
    }
    float4 sm = make_float4(0.f, 0.f, 0.f, 0.f);
    for (int j = lane; j < deg; j += 32) {
        int s = g_csr[base + j];
        float4 a = ((const float4*)g_as1)[s];
        sm.x += __expf(lrelu(a.x + ad.x, NEG_ATT) - mx.x);
        sm.y += __expf(lrelu(a.y + ad.y, NEG_ATT) - mx.y);
        sm.z += __expf(lrelu(a.z + ad.z, NEG_ATT) - mx.z);
        sm.w += __expf(lrelu(a.w + ad.w, NEG_ATT) - mx.w);
    }
#pragma unroll
    for (int off = 16; off > 0; off >>= 1) {
        sm.x += __shfl_xor_sync(0xffffffffu, sm.x, off);
        sm.y += __shfl_xor_sync(0xffffffffu, sm.y, off);
        sm.z += __shfl_xor_sync(0xffffffffu, sm.z, off);
        sm.w += __shfl_xor_sync(0xffffffffu, sm.w, off);
    }
    float4 rv = make_float4(1.f / sm.x, 1.f / sm.y, 1.f / sm.z, 1.f / sm.w);
    for (int j = lane; j < deg; j += 32) {
        int s = g_csr[base + j];
        float4 a = ((const float4*)g_as1)[s];
        float4 al;
        al.x = __expf(lrelu(a.x + ad.x, NEG_ATT) - mx.x) * rv.x;
        al.y = __expf(lrelu(a.y + ad.y, NEG_ATT) - mx.y) * rv.y;
        al.z = __expf(lrelu(a.z + ad.z, NEG_ATT) - mx.z) * rv.z;
        al.w = __expf(lrelu(a.w + ad.w, NEG_ATT) - mx.w) * rv.w;
        ((float4*)g_alE1)[base + j] = al;
    }
}

// ---------------- GAT layer 1 aggregation ------------------------------------
__global__ __launch_bounds__(256) void k_gat1(const float* __restrict__ b1) {
    int n = blockIdx.x;
    int t = threadIdx.x;
    __shared__ int s_src[256];
    __shared__ float s_alpha[256 * 4];
    int base = g_offs[n], deg = g_offs[n + 1] - base;
    int myh = t >> 6;
    float acc = 0.f;
    for (int cb = 0; cb < deg; cb += 256) {
        int len = min(256, deg - cb);
        if (t < len) {
            s_src[t] = g_csr[base + cb + t];
            *(float4*)&s_alpha[t * 4] = ((const float4*)g_alE1)[base + cb + t];
        }
        __syncthreads();
        int j = 0;
        for (; j + 8 <= len; j += 8) {
            float a0 = s_alpha[(j + 0) * 4 + myh];
            float a1 = s_alpha[(j + 1) * 4 + myh];
            float a2 = s_alpha[(j + 2) * 4 + myh];
            float a3 = s_alpha[(j + 3) * 4 + myh];
            float a4 = s_alpha[(j + 4) * 4 + myh];
            float a5 = s_alpha[(j + 5) * 4 + myh];
            float a6 = s_alpha[(j + 6) * 4 + myh];
            float a7 = s_alpha[(j + 7) * 4 + myh];
            float v0 = g_h1[s_src[j + 0] * HC + t];
            float v1 = g_h1[s_src[j + 1] * HC + t];
            float v2 = g_h1[s_src[j + 2] * HC + t];
            float v3 = g_h1[s_src[j + 3] * HC + t];
            float v4 = g_h1[s_src[j + 4] * HC + t];
            float v5 = g_h1[s_src[j + 5] * HC + t];
            float v6 = g_h1[s_src[j + 6] * HC + t];
            float v7 = g_h1[s_src[j + 7] * HC + t];
            acc = fmaf(a0, v0, acc); acc = fmaf(a1, v1, acc);
            acc = fmaf(a2, v2, acc); acc = fmaf(a3, v3, acc);
            acc = fmaf(a4, v4, acc); acc = fmaf(a5, v5, acc);
            acc = fmaf(a6, v6, acc); acc = fmaf(a7, v7, acc);
        }
        for (; j < len; j++)
            acc = fmaf(s_alpha[j * 4 + myh], g_h1[s_src[j] * HC + t], acc);
        __syncthreads();
    }
    g_agg1[n * HC + t] = acc + b1[t];
}

// ---------------- BatchNorm stats --------------------------------------------
__global__ __launch_bounds__(256) void k_bn_partial() {
    int t = threadIdx.x;
    int b = blockIdx.x;
    const int RPB = (NN + 255) / 256;  // 196
    int rs = b * RPB, re = min(NN, rs + RPB);
    float sum = 0.f, sq = 0.f;
    for (int r = rs; r < re; r++) {
        float v = g_agg1[r * HC + t];
        sum += v;
        sq = fmaf(v, v, sq);
    }
    atomicAdd(&g_bnsum[t], sum);
    atomicAdd(&g_bnsq[t], sq);
}

__global__ void k_bn_final(const float* __restrict__ gamma, const float* __restrict__ beta) {
    int t = threadIdx.x;
    if (t < HC) {
        float mean = g_bnsum[t] / (float)NN;
        float var = g_bnsq[t] / (float)NN - mean * mean;
        float rstd = rsqrtf(var + BN_EPS);
        float sc = gamma[t] * rstd;
        g_scale[t] = sc;
        g_shift[t] = beta[t] - mean * sc;
    }
}

// ---------------- GEMM2: fused BN+leaky+split load, alpha2 epilogue ----------
// grid 391, 256 threads. Warp w: rows [bx*128+w*16, +16), all 64 cols.
__global__ __launch_bounds__(256) void k_gemm2(const float* __restrict__ a_src,
                                               const float* __restrict__ a_dst) {
    __shared__ uint4 bs[8][4][32];     // 16 KB
    __shared__ float s_sc[HC], s_sh[HC];
    int t = threadIdx.x;
    int w = t >> 5, lane = t & 31;
    int g = lane >> 2, q = lane & 3;
    int m0 = blockIdx.x * 128 + w * 16 + g;
    int m1 = m0 + 8;
    bool v0 = m0 < NN, v1 = m1 < NN;
    for (int i = t; i < HC; i += 256) { s_sc[i] = g_scale[i]; s_sh[i] = g_shift[i]; }

    float acc[8][4];
#pragma unroll
    for (int nt = 0; nt < 8; nt++)
#pragma unroll
        for (int r = 0; r < 4; r++) acc[nt][r] = 0.f;

    for (int kq = 0; kq < 4; kq++) {
        const uint4* srcw = g_wf2 + kq * 1024;
        for (int i = t; i < 1024; i += 256) ((uint4*)bs)[i] = srcw[i];
        __syncthreads();
#pragma unroll
        for (int kt = 0; kt < 4; kt++) {
            int kk = kq * 64 + kt * 16 + 2 * q;
            float sc0 = s_sc[kk], sh0 = s_sh[kk];
            float sc1 = s_sc[kk + 1], sh1 = s_sh[kk + 1];
            float sc8 = s_sc[kk + 8], sh8 = s_sh[kk + 8];
            float sc9 = s_sc[kk + 9], sh9 = s_sh[kk + 9];
            uint32_t ah0 = 0, ah1 = 0, ah2 = 0, ah3 = 0;
            uint32_t al0 = 0, al1 = 0, al2 = 0, al3 = 0;
            if (v0) {
                float2 u = *(const float2*)&g_agg1[m0 * HC + kk];
                float2 v = *(const float2*)&g_agg1[m0 * HC + kk + 8];
                u.x = lrelu(fmaf(sc0, u.x, sh0), NEG_ACT);
                u.y = lrelu(fmaf(sc1, u.y, sh1), NEG_ACT);
                v.x = lrelu(fmaf(sc8, v.x, sh8), NEG_ACT);
                v.y = lrelu(fmaf(sc9, v.y, sh9), NEG_ACT);
                split2(u, ah0, al0);
                split2(v, ah2, al2);
            }
            if (v1) {
                float2 u = *(const float2*)&g_agg1[m1 * HC + kk];
                float2 v = *(const float2*)&g_agg1[m1 * HC + kk + 8];
                u.x = lrelu(fmaf(sc0, u.x, sh0), NEG_ACT);
                u.y = lrelu(fmaf(sc1, u.y, sh1), NEG_ACT);
                v.x = lrelu(fmaf(sc8, v.x, sh8), NEG_ACT);
                v.y = lrelu(fmaf(sc9, v.y, sh9), NEG_ACT);
                split2(u, ah1, al1);
                split2(v, ah3, al3);
            }
#pragma unroll
            for (int nt = 0; nt < 8; nt++) {
                uint4 b = bs[nt][kt][lane];
                mma16816(acc[nt], ah0, ah1, ah2, ah3, b.x, b.y);
                mma16816(acc[nt], ah0, ah1, ah2, ah3, b.z, b.w);
                mma16816(acc[nt], al0, al1, al2, al3, b.x, b.y);
            }
        }
        __syncthreads();
    }
#pragma unroll
    for (int nt = 0; nt < 8; nt++) {
        int col = nt * 8 + 2 * q;
        if (v0) *(float2*)&g_h2[m0 * C2 + col] = make_float2(acc[nt][0], acc[nt][1]);
        if (v1) *(float2*)&g_h2[m1 * C2 + col] = make_float2(acc[nt][2], acc[nt][3]);
    }

    // fused alpha2 (single head over all 64 cols)
    float ps0 = 0.f, ps1 = 0.f, pd0 = 0.f, pd1 = 0.f;
#pragma unroll
    for (int nt = 0; nt < 8; nt++) {
        int c0 = nt * 8 + 2 * q;
        float s0 = a_src[c0], s1 = a_src[c0 + 1];
        float d0 = a_dst[c0], d1 = a_dst[c0 + 1];
        ps0 += acc[nt][0] * s0 + acc[nt][1] * s1;
        pd0 += acc[nt][0] * d0 + acc[nt][1] * d1;
        ps1 += acc[nt][2] * s0 + acc[nt][3] * s1;
        pd1 += acc[nt][2] * d0 + acc[nt][3] * d1;
    }
#pragma unroll
    for (int off = 1; off <= 2; off <<= 1) {
        ps0 += __shfl_xor_sync(0xffffffffu, ps0, off);
        ps1 += __shfl_xor_sync(0xffffffffu, ps1, off);
        pd0 += __shfl_xor_sync(0xffffffffu, pd0, off);
        pd1 += __shfl_xor_sync(0xffffffffu, pd1, off);
    }
    if (q == 0) {
        if (v0) { g_as2[m0] = ps0; g_ad2[m0] = pd0; }
        if (v1) { g_as2[m1] = ps1; g_ad2[m1] = pd1; }
    }
}

// ---------------- softmax stats layer 2: warp per node, writes edge alphas ---
__global__ __launch_bounds__(256) void k_soft2() {
    int w = threadIdx.x >> 5, lane = threadIdx.x & 31;
    int n = blockIdx.x * 8 + w;
    if (n >= NN) return;
    int base = g_offs[n], deg = g_offs[n + 1] - base;
    float ad = g_ad2[n];
    float mx = -1e30f;
    for (int j = lane; j < deg; j += 32) {
        int s = g_csr[base + j];
        mx = fmaxf(mx, lrelu(g_as2[s] + ad, NEG_ATT));
    }
#pragma unroll
    for (int off = 16; off > 0; off >>= 1)
        mx = fmaxf(mx, __shfl_xor_sync(0xffffffffu, mx, off));
    float sm = 0.f;
    for (int j = lane; j < deg; j += 32) {
        int s = g_csr[base + j];
        sm += __expf(lrelu(g_as2[s] + ad, NEG_ATT) - mx);
    }
#pragma unroll
    for (int off = 16; off > 0; off >>= 1)
        sm += __shfl_xor_sync(0xffffffffu, sm, off);
    float ri = 1.f / sm;
    for (int j = lane; j < deg; j += 32) {
        int s = g_csr[base + j];
        g_alE2[base + j] = __expf(lrelu(g_as2[s] + ad, NEG_ATT) - mx) * ri;
    }
}

// ---------------- GAT layer 2 → output ---------------------------------------
__global__ __launch_bounds__(64) void k_gat2(const float* __restrict__ b2,
                                             float* __restrict__ out) {
    int n = blockIdx.x;
    int t = threadIdx.x;
    __shared__ int ssrc[64];
    __shared__ float sal[64];
    int base = g_offs[n];
    int deg = g_offs[n + 1] - base;

    float acc = 0.f;
    for (int cb = 0; cb < deg; cb += 64) {
        int len = min(64, deg - cb);
        if (t < len) {
            ssrc[t] = g_csr[base + cb + t];
            sal[t] = g_alE2[base + cb + t];
        }
        __syncthreads();
        int j = 0;
        for (; j + 8 <= len; j += 8) {
            float a0 = sal[j + 0], a1 = sal[j + 1], a2 = sal[j + 2], a3 = sal[j + 3];
            float a4 = sal[j + 4], a5 = sal[j + 5], a6 = sal[j + 6], a7 = sal[j + 7];
            float v0 = g_h2[ssrc[j + 0] * C2 + t];
            float v1 = g_h2[ssrc[j + 1] * C2 + t];
            float v2 = g_h2[ssrc[j + 2] * C2 + t];
            float v3 = g_h2[ssrc[j + 3] * C2 + t];
            float v4 = g_h2[ssrc[j + 4] * C2 + t];
            float v5 = g_h2[ssrc[j + 5] * C2 + t];
            float v6 = g_h2[ssrc[j + 6] * C2 + t];
            float v7 = g_h2[ssrc[j + 7] * C2 + t];
            acc = fmaf(a0, v0, acc); acc = fmaf(a1, v1, acc);
            acc = fmaf(a2, v2, acc); acc = fmaf(a3, v3, acc);
            acc = fmaf(a4, v4, acc); acc = fmaf(a5, v5, acc);
            acc = fmaf(a6, v6, acc); acc = fmaf(a7, v7, acc);
        }
        for (; j < len; j++)
            acc = fmaf(sal[j], g_h2[ssrc[j] * C2 + t], acc);
        __syncthreads();
    }
    out[n * C2 + t] = acc + b2[t];
}

// ---------------- launch -----------------------------------------------------
extern "C" void kernel_launch(void* const* d_in, const int* in_sizes, int n_in,
                              void* d_out, int out_size) {
    const float* x      = (const float*)d_in[0];
    const int*   ei     = (const int*)d_in[1];
    const float* W1     = (const float*)d_in[2];
    const float* a_src1 = (const float*)d_in[3];
    const float* a_dst1 = (const float*)d_in[4];
    const float* b1     = (const float*)d_in[5];
    const float* gamma  = (const float*)d_in[6];
    const float* beta   = (const float*)d_in[7];
    const float* W2     = (const float*)d_in[8];
    const float* a_src2 = (const float*)d_in[9];
    const float* a_dst2 = (const float*)d_in[10];
    const float* b2     = (const float*)d_in[11];
    float* out = (float*)d_out;

    const int* src = ei;
    const int* dst = ei + EE;

    // CSR build
    k_init<<<(NN + 255) / 256, 256>>>();
    k_hist<<<(EE + 255) / 256, 256>>>(dst);
    k_scan_block<<<(NN + 1023) / 1024, 1024>>>();
    k_scan_finish<<<(NN + 255) / 256, 256>>>();
    k_scatter<<<(EE + 255) / 256, 256>>>(src, dst);

    // W fragment prep
    k_prep_w1<<<32, 256>>>(W1);
    k_prep_w2<<<16, 256>>>(W2);

    // Layer 1
    k_gemm1<<<dim3((NN + 127) / 128, 2), 256>>>(x, a_src1, a_dst1);
    k_soft1<<<(NN + 7) / 8, 256>>>();
    k_gat1<<<NN, 256>>>(b1);

    // BatchNorm
    k_bn_partial<<<256, 256>>>();
    k_bn_final<<<1, 256>>>(gamma, beta);

    // Layer 2 (BN+leaky fused into GEMM2 load)
    k_gemm2<<<(NN + 127) / 128, 256>>>(a_src2, a_dst2);
    k_soft2<<<(NN + 7) / 8, 256>>>();
    k_gat2<<<NN, 64>>>(b2, out);
}

// round 8
// speedup vs baseline: 2.2549x; 1.2746x over previous
#include <cuda_runtime.h>
#include <cuda_bf16.h>
#include <cuda_fp16.h>
#include <math.h>
#include <stdint.h>

#define NN 50000
#define EE 800000
#define FIN 128
#define HC 256      // HEADS*HID = 4*64
#define HEADS 4
#define HID 64
#define C2 64       // CLASSES
#define ETOT (EE + NN)
#define NEG_ATT 0.2f
#define NEG_ACT 0.01f
#define BN_EPS 1e-5f

// ---------------- scratch (device globals; no allocation allowed) ------------
__device__ int   g_counts[NN];
__device__ int   g_incl[NN];
__device__ int   g_bsum[64];
__device__ int   g_offs[NN + 1];
__device__ int   g_cursor[NN];
__device__ int   g_csr[ETOT];

__device__ __half2 g_h1h[NN * (HC / 2)];   // x @ W1 as fp16 pairs (gather input)
__device__ __half2 g_h2h[NN * (C2 / 2)];   // hn @ W2 as fp16 pairs
__device__ float g_as1[NN * HEADS];
__device__ float g_ad1[NN * HEADS];
__device__ float g_agg1[NN * HC];    // GAT1 output (+b1), fp32
__device__ float g_bnsum[HC];
__device__ float g_bnsq[HC];
__device__ float g_scale[HC];
__device__ float g_shift[HC];
__device__ float g_as2[NN];
__device__ float g_ad2[NN];

// W fragments, fragment-linear: W1: [nhalf(2)][khalf(2)][nt(16)][kt(4)][lane(32)] uint4
__device__ uint4 g_wf1[2 * 2 * 16 * 4 * 32];   // 8192
// W2: [kq(4)][nt(8)][kt(4)][lane(32)] uint4
__device__ uint4 g_wf2[4 * 8 * 4 * 32];        // 4096

// per-edge normalized attention weights (layer 1)
__device__ float g_alE1[ETOT * 4];   // 13.6 MB

__device__ __forceinline__ float lrelu(float v, float s) { return v > 0.f ? v : s * v; }

__device__ __forceinline__ uint32_t pack_bf(float a, float b) {
    __nv_bfloat16 ba = __float2bfloat16(a);
    __nv_bfloat16 bb = __float2bfloat16(b);
    uint16_t ua = *(uint16_t*)&ba;
    uint16_t ub = *(uint16_t*)&bb;
    return (uint32_t)ua | ((uint32_t)ub << 16);
}

// split a float2 into bf16 hi pair + bf16 lo-residual pair
__device__ __forceinline__ void split2(float2 u, uint32_t& hi, uint32_t& lo) {
    float hx = __bfloat162float(__float2bfloat16(u.x));
    float hy = __bfloat162float(__float2bfloat16(u.y));
    hi = pack_bf(hx, hy);
    lo = pack_bf(u.x - hx, u.y - hy);
}

__device__ __forceinline__ void mma16816(float* c, uint32_t a0, uint32_t a1,
                                         uint32_t a2, uint32_t a3,
                                         uint32_t b0, uint32_t b1) {
    asm volatile(
        "mma.sync.aligned.m16n8k16.row.col.f32.bf16.bf16.f32 "
        "{%0,%1,%2,%3}, {%4,%5,%6,%7}, {%8,%9}, {%0,%1,%2,%3};\n"
        : "+f"(c[0]), "+f"(c[1]), "+f"(c[2]), "+f"(c[3])
        : "r"(a0), "r"(a1), "r"(a2), "r"(a3), "r"(b0), "r"(b1));
}

// ---------------- CSR build --------------------------------------------------
__global__ void k_init() {
    int i = blockIdx.x * blockDim.x + threadIdx.x;
    if (i < NN) g_counts[i] = 1;          // self loop pre-counted
    if (i < HC) { g_bnsum[i] = 0.f; g_bnsq[i] = 0.f; }
}

__global__ void k_hist(const int* __restrict__ dst) {
    int e = blockIdx.x * blockDim.x + threadIdx.x;
    if (e < EE) atomicAdd(&g_counts[dst[e]], 1);
}

__global__ void k_scan_block() {   // grid 49, 1024 threads
    __shared__ int sd[1024];
    int t = threadIdx.x;
    int i = blockIdx.x * 1024 + t;
    int v = (i < NN) ? g_counts[i] : 0;
    sd[t] = v;
    __syncthreads();
    for (int off = 1; off < 1024; off <<= 1) {
        int add = (t >= off) ? sd[t - off] : 0;
        __syncthreads();
        sd[t] += add;
        __syncthreads();
    }
    if (i < NN) g_incl[i] = sd[t];
    if (t == 1023) g_bsum[blockIdx.x] = sd[1023];
}

// finish scan, insert self-loop at slot 0 of each node, set cursor
__global__ void k_scan_finish() {
    __shared__ int s_pref;
    int b = blockIdx.x;
    int t = threadIdx.x;
    int i = b * 256 + t;
    if (t == 0) {
        int chunk = b >> 2;        // all 256 indices share i>>10
        int run = 0;
        for (int c = 0; c < chunk; c++) run += g_bsum[c];
        s_pref = run;
    }
    __syncthreads();
    if (i < NN) {
        int incl = g_incl[i] + s_pref;
        g_offs[i + 1] = incl;
        int start = incl - g_counts[i];
        g_csr[start] = i;          // self loop occupies first slot
        g_cursor[i] = start + 1;
        if (i == 0) g_offs[0] = 0;
    }
}

__global__ void k_scatter(const int* __restrict__ src, const int* __restrict__ dst) {
    int e = blockIdx.x * blockDim.x + threadIdx.x;
    if (e < EE) {
        int d = dst[e];
        int pos = atomicAdd(&g_cursor[d], 1);
        g_csr[pos] = src[e];
    }
}

// ---------------- W fragment prep --------------------------------------------
__global__ void k_prep_w1(const float* __restrict__ W) {  // W: [128][256]
    int i = blockIdx.x * blockDim.x + threadIdx.x;
    if (i >= 8192) return;
    int lane = i & 31;
    int kt = (i >> 5) & 3;
    int nt = (i >> 7) & 15;
    int kh = (i >> 11) & 1;
    int nh = (i >> 12) & 1;
    int g = lane >> 2, q = lane & 3;
    int k = kh * 64 + kt * 16 + 2 * q;
    int n = nh * 128 + nt * 8 + g;
    float w00 = W[k * HC + n];
    float w01 = W[(k + 1) * HC + n];
    float w10 = W[(k + 8) * HC + n];
    float w11 = W[(k + 9) * HC + n];
    float h00 = __bfloat162float(__float2bfloat16(w00));
    float h01 = __bfloat162float(__float2bfloat16(w01));
    float h10 = __bfloat162float(__float2bfloat16(w10));
    float h11 = __bfloat162float(__float2bfloat16(w11));
    g_wf1[i] = make_uint4(pack_bf(h00, h01), pack_bf(h10, h11),
                          pack_bf(w00 - h00, w01 - h01), pack_bf(w10 - h10, w11 - h11));
}

__global__ void k_prep_w2(const float* __restrict__ W) {  // W: [256][64]
    int i = blockIdx.x * blockDim.x + threadIdx.x;
    if (i >= 4096) return;
    int lane = i & 31;
    int kt = (i >> 5) & 3;
    int nt = (i >> 7) & 7;
    int kq = (i >> 10) & 3;
    int g = lane >> 2, q = lane & 3;
    int k = kq * 64 + kt * 16 + 2 * q;
    int n = nt * 8 + g;
    float w00 = W[k * C2 + n];
    float w01 = W[(k + 1) * C2 + n];
    float w10 = W[(k + 8) * C2 + n];
    float w11 = W[(k + 9) * C2 + n];
    float h00 = __bfloat162float(__float2bfloat16(w00));
    float h01 = __bfloat162float(__float2bfloat16(w01));
    float h10 = __bfloat162float(__float2bfloat16(w10));
    float h11 = __bfloat162float(__float2bfloat16(w11));
    g_wf2[i] = make_uint4(pack_bf(h00, h01), pack_bf(h10, h11),
                          pack_bf(w00 - h00, w01 - h01), pack_bf(w10 - h10, w11 - h11));
}

// ---------------- GEMM1: h1 = x @ W1, fp16 store + alpha1 epilogue ----------
// grid (391, 2), 256 threads. Warp w: rows [bx*128+w*16, +16), cols nh*128..+128
__global__ __launch_bounds__(256) void k_gemm1(const float* __restrict__ x,
                                               const float* __restrict__ a_src,
                                               const float* __restrict__ a_dst) {
    __shared__ uint4 bs[16][4][32];    // 32 KB
    int t = threadIdx.x;
    int w = t >> 5, lane = t & 31;
    int g = lane >> 2, q = lane & 3;
    int m0 = blockIdx.x * 128 + w * 16 + g;
    int m1 = m0 + 8;
    bool v0 = m0 < NN, v1 = m1 < NN;
    int nh = blockIdx.y;

    float acc[16][4];
#pragma unroll
    for (int nt = 0; nt < 16; nt++)
#pragma unroll
        for (int r = 0; r < 4; r++) acc[nt][r] = 0.f;

    for (int kh = 0; kh < 2; kh++) {
        const uint4* srcw = g_wf1 + (nh * 2 + kh) * 2048;
        for (int i = t; i < 2048; i += 256) ((uint4*)bs)[i] = srcw[i];
        __syncthreads();
#pragma unroll
        for (int kt = 0; kt < 4; kt++) {
            int kk = kh * 64 + kt * 16 + 2 * q;
            uint32_t ah0 = 0, ah1 = 0, ah2 = 0, ah3 = 0;
            uint32_t al0 = 0, al1 = 0, al2 = 0, al3 = 0;
            if (v0) {
                split2(*(const float2*)&x[m0 * FIN + kk], ah0, al0);
                split2(*(const float2*)&x[m0 * FIN + kk + 8], ah2, al2);
            }
            if (v1) {
                split2(*(const float2*)&x[m1 * FIN + kk], ah1, al1);
                split2(*(const float2*)&x[m1 * FIN + kk + 8], ah3, al3);
            }
#pragma unroll
            for (int nt = 0; nt < 16; nt++) {
                uint4 b = bs[nt][kt][lane];
                mma16816(acc[nt], ah0, ah1, ah2, ah3, b.x, b.y);  // hi*hi
                mma16816(acc[nt], ah0, ah1, ah2, ah3, b.z, b.w);  // hi*lo
                mma16816(acc[nt], al0, al1, al2, al3, b.x, b.y);  // lo*hi
            }
        }
        __syncthreads();
    }
    int nbase = nh * 128;
#pragma unroll
    for (int nt = 0; nt < 16; nt++) {
        int hidx = (nbase >> 1) + nt * 4 + q;
        if (v0) g_h1h[m0 * (HC / 2) + hidx] = __float22half2_rn(make_float2(acc[nt][0], acc[nt][1]));
        if (v1) g_h1h[m1 * (HC / 2) + hidx] = __float22half2_rn(make_float2(acc[nt][2], acc[nt][3]));
    }

    // fused alpha: per-head dot with a_src / a_dst (heads align with nt groups)
    float ps[2][2] = {{0.f, 0.f}, {0.f, 0.f}};
    float pd[2][2] = {{0.f, 0.f}, {0.f, 0.f}};
#pragma unroll
    for (int nt = 0; nt < 16; nt++) {
        int hl = nt >> 3;
        int c0 = nbase + nt * 8 + 2 * q;
        float s0 = a_src[c0], s1 = a_src[c0 + 1];
        float d0 = a_dst[c0], d1 = a_dst[c0 + 1];
        ps[hl][0] += acc[nt][0] * s0 + acc[nt][1] * s1;
        pd[hl][0] += acc[nt][0] * d0 + acc[nt][1] * d1;
        ps[hl][1] += acc[nt][2] * s0 + acc[nt][3] * s1;
        pd[hl][1] += acc[nt][2] * d0 + acc[nt][3] * d1;
    }
#pragma unroll
    for (int off = 1; off <= 2; off <<= 1) {
#pragma unroll
        for (int hl = 0; hl < 2; hl++) {
            ps[hl][0] += __shfl_xor_sync(0xffffffffu, ps[hl][0], off);
            ps[hl][1] += __shfl_xor_sync(0xffffffffu, ps[hl][1], off);
            pd[hl][0] += __shfl_xor_sync(0xffffffffu, pd[hl][0], off);
            pd[hl][1] += __shfl_xor_sync(0xffffffffu, pd[hl][1], off);
        }
    }
    if (q == 0) {
#pragma unroll
        for (int hl = 0; hl < 2; hl++) {
            int gh = nh * 2 + hl;
            if (v0) { g_as1[m0 * 4 + gh] = ps[hl][0]; g_ad1[m0 * 4 + gh] = pd[hl][0]; }
            if (v1) { g_as1[m1 * 4 + gh] = ps[hl][1]; g_ad1[m1 * 4 + gh] = pd[hl][1]; }
        }
    }
}

// ---------------- softmax stats layer 1: warp per node, writes edge alphas ---
__global__ __launch_bounds__(256) void k_soft1() {
    int w = threadIdx.x >> 5, lane = threadIdx.x & 31;
    int n = blockIdx.x * 8 + w;
    if (n >= NN) return;
    int base = g_offs[n], deg = g_offs[n + 1] - base;
    float4 ad = ((const float4*)g_ad1)[n];
    float4 mx = make_float4(-1e30f, -1e30f, -1e30f, -1e30f);
    for (int j = lane; j < deg; j += 32) {
        int s = g_csr[base + j];
        float4 a = ((const float4*)g_as1)[s];
        mx.x = fmaxf(mx.x, lrelu(a.x + ad.x, NEG_ATT));
        mx.y = fmaxf(mx.y, lrelu(a.y + ad.y, NEG_ATT));
        mx.z = fmaxf(mx.z, lrelu(a.z + ad.z, NEG_ATT));
        mx.w = fmaxf(mx.w, lrelu(a.w + ad.w, NEG_ATT));
    }
#pragma unroll
    for (int off = 16; off > 0; off >>= 1) {
        mx.x = fmaxf(mx.x, __shfl_xor_sync(0xffffffffu, mx.x, off));
        mx.y = fmaxf(mx.y, __shfl_xor_sync(0xffffffffu, mx.y, off));
        mx.z = fmaxf(mx.z, __shfl_xor_sync(0xffffffffu, mx.z, off));
        mx.w = fmaxf(mx.w, __shfl_xor_sync(0xffffffffu, mx.w, off));
    }
    float4 sm = make_float4(0.f, 0.f, 0.f, 0.f);
    for (int j = lane; j < deg; j += 32) {
        int s = g_csr[base + j];
        float4 a = ((const float4*)g_as1)[s];
        sm.x += __expf(lrelu(a.x + ad.x, NEG_ATT) - mx.x);
        sm.y += __expf(lrelu(a.y + ad.y, NEG_ATT) - mx.y);
        sm.z += __expf(lrelu(a.z + ad.z, NEG_ATT) - mx.z);
        sm.w += __expf(lrelu(a.w + ad.w, NEG_ATT) - mx.w);
    }
#pragma unroll
    for (int off = 16; off > 0; off >>= 1) {
        sm.x += __shfl_xor_sync(0xffffffffu, sm.x, off);
        sm.y += __shfl_xor_sync(0xffffffffu, sm.y, off);
        sm.z += __shfl_xor_sync(0xffffffffu, sm.z, off);
        sm.w += __shfl_xor_sync(0xffffffffu, sm.w, off);
    }
    float4 rv = make_float4(1.f / sm.x, 1.f / sm.y, 1.f / sm.z, 1.f / sm.w);
    for (int j = lane; j < deg; j += 32) {
        int s = g_csr[base + j];
        float4 a = ((const float4*)g_as1)[s];
        float4 al;
        al.x = __expf(lrelu(a.x + ad.x, NEG_ATT) - mx.x) * rv.x;
        al.y = __expf(lrelu(a.y + ad.y, NEG_ATT) - mx.y) * rv.y;
        al.z = __expf(lrelu(a.z + ad.z, NEG_ATT) - mx.z) * rv.z;
        al.w = __expf(lrelu(a.w + ad.w, NEG_ATT) - mx.w) * rv.w;
        ((float4*)g_alE1)[base + j] = al;
    }
}

// ---------------- GAT layer 1 aggregation (fp16 gather, half2/thread) --------
__global__ __launch_bounds__(128) void k_gat1(const float* __restrict__ b1) {
    int n = blockIdx.x;
    int t = threadIdx.x;                 // covers channels 2t, 2t+1
    __shared__ int s_src[128];
    __shared__ float s_alpha[128 * 4];
    int base = g_offs[n], deg = g_offs[n + 1] - base;
    int myh = t >> 5;                    // head = (2t)/64
    float ax = 0.f, ay = 0.f;
    for (int cb = 0; cb < deg; cb += 128) {
        int len = min(128, deg - cb);
        if (t < len) {
            s_src[t] = g_csr[base + cb + t];
            *(float4*)&s_alpha[t * 4] = ((const float4*)g_alE1)[base + cb + t];
        }
        __syncthreads();
        int j = 0;
        for (; j + 8 <= len; j += 8) {
            float a0 = s_alpha[(j + 0) * 4 + myh];
            float a1 = s_alpha[(j + 1) * 4 + myh];
            float a2 = s_alpha[(j + 2) * 4 + myh];
            float a3 = s_alpha[(j + 3) * 4 + myh];
            float a4 = s_alpha[(j + 4) * 4 + myh];
            float a5 = s_alpha[(j + 5) * 4 + myh];
            float a6 = s_alpha[(j + 6) * 4 + myh];
            float a7 = s_alpha[(j + 7) * 4 + myh];
            float2 f0 = __half22float2(g_h1h[s_src[j + 0] * (HC / 2) + t]);
            float2 f1 = __half22float2(g_h1h[s_src[j + 1] * (HC / 2) + t]);
            float2 f2 = __half22float2(g_h1h[s_src[j + 2] * (HC / 2) + t]);
            float2 f3 = __half22float2(g_h1h[s_src[j + 3] * (HC / 2) + t]);
            float2 f4 = __half22float2(g_h1h[s_src[j + 4] * (HC / 2) + t]);
            float2 f5 = __half22float2(g_h1h[s_src[j + 5] * (HC / 2) + t]);
            float2 f6 = __half22float2(g_h1h[s_src[j + 6] * (HC / 2) + t]);
            float2 f7 = __half22float2(g_h1h[s_src[j + 7] * (HC / 2) + t]);
            ax = fmaf(a0, f0.x, ax); ay = fmaf(a0, f0.y, ay);
            ax = fmaf(a1, f1.x, ax); ay = fmaf(a1, f1.y, ay);
            ax = fmaf(a2, f2.x, ax); ay = fmaf(a2, f2.y, ay);
            ax = fmaf(a3, f3.x, ax); ay = fmaf(a3, f3.y, ay);
            ax = fmaf(a4, f4.x, ax); ay = fmaf(a4, f4.y, ay);
            ax = fmaf(a5, f5.x, ax); ay = fmaf(a5, f5.y, ay);
            ax = fmaf(a6, f6.x, ax); ay = fmaf(a6, f6.y, ay);
            ax = fmaf(a7, f7.x, ax); ay = fmaf(a7, f7.y, ay);
        }
        for (; j < len; j++) {
            float a = s_alpha[j * 4 + myh];
            float2 f = __half22float2(g_h1h[s_src[j] * (HC / 2) + t]);
            ax = fmaf(a, f.x, ax); ay = fmaf(a, f.y, ay);
        }
        __syncthreads();
    }
    *(float2*)&g_agg1[n * HC + 2 * t] = make_float2(ax + b1[2 * t], ay + b1[2 * t + 1]);
}

// ---------------- BatchNorm stats --------------------------------------------
__global__ __launch_bounds__(256) void k_bn_partial() {
    int t = threadIdx.x;
    int b = blockIdx.x;
    const int RPB = (NN + 255) / 256;  // 196
    int rs = b * RPB, re = min(NN, rs + RPB);
    float sum = 0.f, sq = 0.f;
    for (int r = rs; r < re; r++) {
        float v = g_agg1[r * HC + t];
        sum += v;
        sq = fmaf(v, v, sq);
    }
    atomicAdd(&g_bnsum[t], sum);
    atomicAdd(&g_bnsq[t], sq);
}

__global__ void k_bn_final(const float* __restrict__ gamma, const float* __restrict__ beta) {
    int t = threadIdx.x;
    if (t < HC) {
        float mean = g_bnsum[t] / (float)NN;
        float var = g_bnsq[t] / (float)NN - mean * mean;
        float rstd = rsqrtf(var + BN_EPS);
        float sc = gamma[t] * rstd;
        g_scale[t] = sc;
        g_shift[t] = beta[t] - mean * sc;
    }
}

// ---------------- GEMM2: fused BN+leaky+split load, fp16 store, alpha2 -------
// grid 391, 256 threads. Warp w: rows [bx*128+w*16, +16), all 64 cols.
__global__ __launch_bounds__(256) void k_gemm2(const float* __restrict__ a_src,
                                               const float* __restrict__ a_dst) {
    __shared__ uint4 bs[8][4][32];     // 16 KB
    __shared__ float s_sc[HC], s_sh[HC];
    int t = threadIdx.x;
    int w = t >> 5, lane = t & 31;
    int g = lane >> 2, q = lane & 3;
    int m0 = blockIdx.x * 128 + w * 16 + g;
    int m1 = m0 + 8;
    bool v0 = m0 < NN, v1 = m1 < NN;
    for (int i = t; i < HC; i += 256) { s_sc[i] = g_scale[i]; s_sh[i] = g_shift[i]; }

    float acc[8][4];
#pragma unroll
    for (int nt = 0; nt < 8; nt++)
#pragma unroll
        for (int r = 0; r < 4; r++) acc[nt][r] = 0.f;

    for (int kq = 0; kq < 4; kq++) {
        const uint4* srcw = g_wf2 + kq * 1024;
        for (int i = t; i < 1024; i += 256) ((uint4*)bs)[i] = srcw[i];
        __syncthreads();
#pragma unroll
        for (int kt = 0; kt < 4; kt++) {
            int kk = kq * 64 + kt * 16 + 2 * q;
            float sc0 = s_sc[kk], sh0 = s_sh[kk];
            float sc1 = s_sc[kk + 1], sh1 = s_sh[kk + 1];
            float sc8 = s_sc[kk + 8], sh8 = s_sh[kk + 8];
            float sc9 = s_sc[kk + 9], sh9 = s_sh[kk + 9];
            uint32_t ah0 = 0, ah1 = 0, ah2 = 0, ah3 = 0;
            uint32_t al0 = 0, al1 = 0, al2 = 0, al3 = 0;
            if (v0) {
                float2 u = *(const float2*)&g_agg1[m0 * HC + kk];
                float2 v = *(const float2*)&g_agg1[m0 * HC + kk + 8];
                u.x = lrelu(fmaf(sc0, u.x, sh0), NEG_ACT);
                u.y = lrelu(fmaf(sc1, u.y, sh1), NEG_ACT);
                v.x = lrelu(fmaf(sc8, v.x, sh8), NEG_ACT);
                v.y = lrelu(fmaf(sc9, v.y, sh9), NEG_ACT);
                split2(u, ah0, al0);
                split2(v, ah2, al2);
            }
            if (v1) {
                float2 u = *(const float2*)&g_agg1[m1 * HC + kk];
                float2 v = *(const float2*)&g_agg1[m1 * HC + kk + 8];
                u.x = lrelu(fmaf(sc0, u.x, sh0), NEG_ACT);
                u.y = lrelu(fmaf(sc1, u.y, sh1), NEG_ACT);
                v.x = lrelu(fmaf(sc8, v.x, sh8), NEG_ACT);
                v.y = lrelu(fmaf(sc9, v.y, sh9), NEG_ACT);
                split2(u, ah1, al1);
                split2(v, ah3, al3);
            }
#pragma unroll
            for (int nt = 0; nt < 8; nt++) {
                uint4 b = bs[nt][kt][lane];
                mma16816(acc[nt], ah0, ah1, ah2, ah3, b.x, b.y);
                mma16816(acc[nt], ah0, ah1, ah2, ah3, b.z, b.w);
                mma16816(acc[nt], al0, al1, al2, al3, b.x, b.y);
            }
        }
        __syncthreads();
    }
#pragma unroll
    for (int nt = 0; nt < 8; nt++) {
        int hidx = nt * 4 + q;
        if (v0) g_h2h[m0 * (C2 / 2) + hidx] = __float22half2_rn(make_float2(acc[nt][0], acc[nt][1]));
        if (v1) g_h2h[m1 * (C2 / 2) + hidx] = __float22half2_rn(make_float2(acc[nt][2], acc[nt][3]));
    }

    // fused alpha2 (single head over all 64 cols)
    float ps0 = 0.f, ps1 = 0.f, pd0 = 0.f, pd1 = 0.f;
#pragma unroll
    for (int nt = 0; nt < 8; nt++) {
        int c0 = nt * 8 + 2 * q;
        float s0 = a_src[c0], s1 = a_src[c0 + 1];
        float d0 = a_dst[c0], d1 = a_dst[c0 + 1];
        ps0 += acc[nt][0] * s0 + acc[nt][1] * s1;
        pd0 += acc[nt][0] * d0 + acc[nt][1] * d1;
        ps1 += acc[nt][2] * s0 + acc[nt][3] * s1;
        pd1 += acc[nt][2] * d0 + acc[nt][3] * d1;
    }
#pragma unroll
    for (int off = 1; off <= 2; off <<= 1) {
        ps0 += __shfl_xor_sync(0xffffffffu, ps0, off);
        ps1 += __shfl_xor_sync(0xffffffffu, ps1, off);
        pd0 += __shfl_xor_sync(0xffffffffu, pd0, off);
        pd1 += __shfl_xor_sync(0xffffffffu, pd1, off);
    }
    if (q == 0) {
        if (v0) { g_as2[m0] = ps0; g_ad2[m0] = pd0; }
        if (v1) { g_as2[m1] = ps1; g_ad2[m1] = pd1; }
    }
}

// ---------------- GAT layer 2: warp per node, fused softmax → output ---------
__global__ __launch_bounds__(128) void k_gat2(const float* __restrict__ b2,
                                              float* __restrict__ out) {
    int w = threadIdx.x >> 5, lane = threadIdx.x & 31;
    int n = blockIdx.x * 4 + w;
    if (n >= NN) return;
    int base = g_offs[n], deg = g_offs[n + 1] - base;
    float ad = g_ad2[n];

    float mx = -1e30f;
    for (int j = lane; j < deg; j += 32) {
        int s = g_csr[base + j];
        mx = fmaxf(mx, lrelu(g_as2[s] + ad, NEG_ATT));
    }
#pragma unroll
    for (int off = 16; off > 0; off >>= 1)
        mx = fmaxf(mx, __shfl_xor_sync(0xffffffffu, mx, off));
    float sm = 0.f;
    for (int j = lane; j < deg; j += 32) {
        int s = g_csr[base + j];
        sm += __expf(lrelu(g_as2[s] + ad, NEG_ATT) - mx);
    }
#pragma unroll
    for (int off = 16; off > 0; off >>= 1)
        sm += __shfl_xor_sync(0xffffffffu, sm, off);
    float ri = 1.f / sm;

    float ax = 0.f, ay = 0.f;
    for (int cb = 0; cb < deg; cb += 32) {
        int len = min(32, deg - cb);
        int myidx = 0;
        float myal = 0.f;
        if (lane < len) {
            myidx = g_csr[base + cb + lane];
            myal = __expf(lrelu(g_as2[myidx] + ad, NEG_ATT) - mx) * ri;
        }
        int j = 0;
        for (; j + 4 <= len; j += 4) {
            int s0 = __shfl_sync(0xffffffffu, myidx, j);
            int s1 = __shfl_sync(0xffffffffu, myidx, j + 1);
            int s2 = __shfl_sync(0xffffffffu, myidx, j + 2);
            int s3 = __shfl_sync(0xffffffffu, myidx, j + 3);
            float a0 = __shfl_sync(0xffffffffu, myal, j);
            float a1 = __shfl_sync(0xffffffffu, myal, j + 1);
            float a2 = __shfl_sync(0xffffffffu, myal, j + 2);
            float a3 = __shfl_sync(0xffffffffu, myal, j + 3);
            float2 f0 = __half22float2(g_h2h[s0 * (C2 / 2) + lane]);
            float2 f1 = __half22float2(g_h2h[s1 * (C2 / 2) + lane]);
            float2 f2 = __half22float2(g_h2h[s2 * (C2 / 2) + lane]);
            float2 f3 = __half22float2(g_h2h[s3 * (C2 / 2) + lane]);
            ax = fmaf(a0, f0.x, ax); ay = fmaf(a0, f0.y, ay);
            ax = fmaf(a1, f1.x, ax); ay = fmaf(a1, f1.y, ay);
            ax = fmaf(a2, f2.x, ax); ay = fmaf(a2, f2.y, ay);
            ax = fmaf(a3, f3.x, ax); ay = fmaf(a3, f3.y, ay);
        }
        for (; j < len; j++) {
            int s = __shfl_sync(0xffffffffu, myidx, j);
            float a = __shfl_sync(0xffffffffu, myal, j);
            float2 f = __half22float2(g_h2h[s * (C2 / 2) + lane]);
            ax = fmaf(a, f.x, ax); ay = fmaf(a, f.y, ay);
        }
    }
    *(float2*)&out[n * C2 + 2 * lane] =
        make_float2(ax + b2[2 * lane], ay + b2[2 * lane + 1]);
}

// ---------------- launch -----------------------------------------------------
extern "C" void kernel_launch(void* const* d_in, const int* in_sizes, int n_in,
                              void* d_out, int out_size) {
    const float* x      = (const float*)d_in[0];
    const int*   ei     = (const int*)d_in[1];
    const float* W1     = (const float*)d_in[2];
    const float* a_src1 = (const float*)d_in[3];
    const float* a_dst1 = (const float*)d_in[4];
    const float* b1     = (const float*)d_in[5];
    const float* gamma  = (const float*)d_in[6];
    const float* beta   = (const float*)d_in[7];
    const float* W2     = (const float*)d_in[8];
    const float* a_src2 = (const float*)d_in[9];
    const float* a_dst2 = (const float*)d_in[10];
    const float* b2     = (const float*)d_in[11];
    float* out = (float*)d_out;

    const int* src = ei;
    const int* dst = ei + EE;

    // CSR build
    k_init<<<(NN + 255) / 256, 256>>>();
    k_hist<<<(EE + 255) / 256, 256>>>(dst);
    k_scan_block<<<(NN + 1023) / 1024, 1024>>>();
    k_scan_finish<<<(NN + 255) / 256, 256>>>();
    k_scatter<<<(EE + 255) / 256, 256>>>(src, dst);

    // W fragment prep
    k_prep_w1<<<32, 256>>>(W1);
    k_prep_w2<<<16, 256>>>(W2);

    // Layer 1
    k_gemm1<<<dim3((NN + 127) / 128, 2), 256>>>(x, a_src1, a_dst1);
    k_soft1<<<(NN + 7) / 8, 256>>>();
    k_gat1<<<NN, 128>>>(b1);

    // BatchNorm
    k_bn_partial<<<256, 256>>>();
    k_bn_final<<<1, 256>>>(gamma, beta);

    // Layer 2 (BN+leaky fused into GEMM2 load; softmax fused into gat2)
    k_gemm2<<<(NN + 127) / 128, 256>>>(a_src2, a_dst2);
    k_gat2<<<(NN + 3) / 4, 128>>>(b2, out);
}

// round 9
// speedup vs baseline: 2.3536x; 1.0438x over previous
#include <cuda_runtime.h>
#include <cuda_bf16.h>
#include <cuda_fp16.h>
#include <math.h>
#include <stdint.h>

#define NN 50000
#define EE 800000
#define FIN 128
#define HC 256      // HEADS*HID = 4*64
#define HEADS 4
#define HID 64
#define C2 64       // CLASSES
#define ETOT (EE + NN)
#define NEG_ATT 0.2f
#define NEG_ACT 0.01f
#define BN_EPS 1e-5f

// ---------------- scratch (device globals; no allocation allowed) ------------
__device__ int   g_counts[NN];
__device__ int   g_incl[NN];
__device__ int   g_bsum[64];
__device__ int   g_offs[NN + 1];
__device__ int   g_cursor[NN];
__device__ int   g_csr[ETOT];

__device__ __half2 g_h1h[NN * (HC / 2)];   // x @ W1 as fp16 pairs (gather input)
__device__ __half2 g_h2h[NN * (C2 / 2)];   // hn @ W2 as fp16 pairs
__device__ __half2 g_agg1h[NN * (HC / 2)]; // GAT1 output (+b1), fp16
__device__ float g_as1[NN * HEADS];
__device__ float g_ad1[NN * HEADS];
__device__ float g_bnsum[HC];
__device__ float g_bnsq[HC];
__device__ float g_scale[HC];
__device__ float g_shift[HC];
__device__ float g_as2[NN];
__device__ float g_ad2[NN];
__device__ int   g_bncnt;

// W fragments, fragment-linear: W1: [nhalf(2)][khalf(2)][nt(16)][kt(4)][lane(32)] uint4
__device__ uint4 g_wf1[2 * 2 * 16 * 4 * 32];   // 8192
// W2: [kq(4)][nt(8)][kt(4)][lane(32)] uint4
__device__ uint4 g_wf2[4 * 8 * 4 * 32];        // 4096

// per-edge normalized attention weights (layer 1)
__device__ float g_alE1[ETOT * 4];   // 13.6 MB

__device__ __forceinline__ float lrelu(float v, float s) { return v > 0.f ? v : s * v; }

__device__ __forceinline__ uint32_t pack_bf(float a, float b) {
    __nv_bfloat16 ba = __float2bfloat16(a);
    __nv_bfloat16 bb = __float2bfloat16(b);
    uint16_t ua = *(uint16_t*)&ba;
    uint16_t ub = *(uint16_t*)&bb;
    return (uint32_t)ua | ((uint32_t)ub << 16);
}

// split a float2 into bf16 hi pair + bf16 lo-residual pair
__device__ __forceinline__ void split2(float2 u, uint32_t& hi, uint32_t& lo) {
    float hx = __bfloat162float(__float2bfloat16(u.x));
    float hy = __bfloat162float(__float2bfloat16(u.y));
    hi = pack_bf(hx, hy);
    lo = pack_bf(u.x - hx, u.y - hy);
}

__device__ __forceinline__ void mma16816(float* c, uint32_t a0, uint32_t a1,
                                         uint32_t a2, uint32_t a3,
                                         uint32_t b0, uint32_t b1) {
    asm volatile(
        "mma.sync.aligned.m16n8k16.row.col.f32.bf16.bf16.f32 "
        "{%0,%1,%2,%3}, {%4,%5,%6,%7}, {%8,%9}, {%0,%1,%2,%3};\n"
        : "+f"(c[0]), "+f"(c[1]), "+f"(c[2]), "+f"(c[3])
        : "r"(a0), "r"(a1), "r"(a2), "r"(a3), "r"(b0), "r"(b1));
}

// ---------------- CSR build --------------------------------------------------
__global__ void k_init() {
    int i = blockIdx.x * blockDim.x + threadIdx.x;
    if (i < NN) g_counts[i] = 1;          // self loop pre-counted
    if (i < HC) { g_bnsum[i] = 0.f; g_bnsq[i] = 0.f; }
    if (i == 0) g_bncnt = 0;
}

__global__ void k_hist(const int* __restrict__ dst) {
    int e = blockIdx.x * blockDim.x + threadIdx.x;
    if (e < EE) atomicAdd(&g_counts[dst[e]], 1);
}

__global__ void k_scan_block() {   // grid 49, 1024 threads
    __shared__ int sd[1024];
    int t = threadIdx.x;
    int i = blockIdx.x * 1024 + t;
    int v = (i < NN) ? g_counts[i] : 0;
    sd[t] = v;
    __syncthreads();
    for (int off = 1; off < 1024; off <<= 1) {
        int add = (t >= off) ? sd[t - off] : 0;
        __syncthreads();
        sd[t] += add;
        __syncthreads();
    }
    if (i < NN) g_incl[i] = sd[t];
    if (t == 1023) g_bsum[blockIdx.x] = sd[1023];
}

// finish scan, insert self-loop at slot 0 of each node, set cursor
__global__ void k_scan_finish() {
    __shared__ int s_pref;
    int b = blockIdx.x;
    int t = threadIdx.x;
    int i = b * 256 + t;
    if (t == 0) {
        int chunk = b >> 2;        // all 256 indices share i>>10
        int run = 0;
        for (int c = 0; c < chunk; c++) run += g_bsum[c];
        s_pref = run;
    }
    __syncthreads();
    if (i < NN) {
        int incl = g_incl[i] + s_pref;
        g_offs[i + 1] = incl;
        int start = incl - g_counts[i];
        g_csr[start] = i;          // self loop occupies first slot
        g_cursor[i] = start + 1;
        if (i == 0) g_offs[0] = 0;
    }
}

__global__ void k_scatter(const int* __restrict__ src, const int* __restrict__ dst) {
    int e = blockIdx.x * blockDim.x + threadIdx.x;
    if (e < EE) {
        int d = dst[e];
        int pos = atomicAdd(&g_cursor[d], 1);
        g_csr[pos] = src[e];
    }
}

// ---------------- W fragment prep (both weights, one launch) -----------------
__global__ void k_prep_w(const float* __restrict__ W1f, const float* __restrict__ W2f) {
    int i = blockIdx.x * blockDim.x + threadIdx.x;
    if (i < 8192) {
        int lane = i & 31;
        int kt = (i >> 5) & 3;
        int nt = (i >> 7) & 15;
        int kh = (i >> 11) & 1;
        int nh = (i >> 12) & 1;
        int g = lane >> 2, q = lane & 3;
        int k = kh * 64 + kt * 16 + 2 * q;
        int n = nh * 128 + nt * 8 + g;
        float w00 = W1f[k * HC + n];
        float w01 = W1f[(k + 1) * HC + n];
        float w10 = W1f[(k + 8) * HC + n];
        float w11 = W1f[(k + 9) * HC + n];
        float h00 = __bfloat162float(__float2bfloat16(w00));
        float h01 = __bfloat162float(__float2bfloat16(w01));
        float h10 = __bfloat162float(__float2bfloat16(w10));
        float h11 = __bfloat162float(__float2bfloat16(w11));
        g_wf1[i] = make_uint4(pack_bf(h00, h01), pack_bf(h10, h11),
                              pack_bf(w00 - h00, w01 - h01), pack_bf(w10 - h10, w11 - h11));
    } else if (i < 8192 + 4096) {
        int j = i - 8192;
        int lane = j & 31;
        int kt = (j >> 5) & 3;
        int nt = (j >> 7) & 7;
        int kq = (j >> 10) & 3;
        int g = lane >> 2, q = lane & 3;
        int k = kq * 64 + kt * 16 + 2 * q;
        int n = nt * 8 + g;
        float w00 = W2f[k * C2 + n];
        float w01 = W2f[(k + 1) * C2 + n];
        float w10 = W2f[(k + 8) * C2 + n];
        float w11 = W2f[(k + 9) * C2 + n];
        float h00 = __bfloat162float(__float2bfloat16(w00));
        float h01 = __bfloat162float(__float2bfloat16(w01));
        float h10 = __bfloat162float(__float2bfloat16(w10));
        float h11 = __bfloat162float(__float2bfloat16(w11));
        g_wf2[j] = make_uint4(pack_bf(h00, h01), pack_bf(h10, h11),
                              pack_bf(w00 - h00, w01 - h01), pack_bf(w10 - h10, w11 - h11));
    }
}

// ---------------- GEMM1: h1 = x @ W1, fp16 store + alpha1 epilogue ----------
// grid (391, 2), 256 threads. Warp w: rows [bx*128+w*16, +16), cols nh*128..+128
__global__ __launch_bounds__(256) void k_gemm1(const float* __restrict__ x,
                                               const float* __restrict__ a_src,
                                               const float* __restrict__ a_dst) {
    __shared__ uint4 bs[16][4][32];    // 32 KB
    int t = threadIdx.x;
    int w = t >> 5, lane = t & 31;
    int g = lane >> 2, q = lane & 3;
    int m0 = blockIdx.x * 128 + w * 16 + g;
    int m1 = m0 + 8;
    bool v0 = m0 < NN, v1 = m1 < NN;
    int nh = blockIdx.y;

    float acc[16][4];
#pragma unroll
    for (int nt = 0; nt < 16; nt++)
#pragma unroll
        for (int r = 0; r < 4; r++) acc[nt][r] = 0.f;

    for (int kh = 0; kh < 2; kh++) {
        const uint4* srcw = g_wf1 + (nh * 2 + kh) * 2048;
        for (int i = t; i < 2048; i += 256) ((uint4*)bs)[i] = srcw[i];
        __syncthreads();
#pragma unroll
        for (int kt = 0; kt < 4; kt++) {
            int kk = kh * 64 + kt * 16 + 2 * q;
            uint32_t ah0 = 0, ah1 = 0, ah2 = 0, ah3 = 0;
            uint32_t al0 = 0, al1 = 0, al2 = 0, al3 = 0;
            if (v0) {
                split2(*(const float2*)&x[m0 * FIN + kk], ah0, al0);
                split2(*(const float2*)&x[m0 * FIN + kk + 8], ah2, al2);
            }
            if (v1) {
                split2(*(const float2*)&x[m1 * FIN + kk], ah1, al1);
                split2(*(const float2*)&x[m1 * FIN + kk + 8], ah3, al3);
            }
#pragma unroll
            for (int nt = 0; nt < 16; nt++) {
                uint4 b = bs[nt][kt][lane];
                mma16816(acc[nt], ah0, ah1, ah2, ah3, b.x, b.y);  // hi*hi
                mma16816(acc[nt], ah0, ah1, ah2, ah3, b.z, b.w);  // hi*lo
                mma16816(acc[nt], al0, al1, al2, al3, b.x, b.y);  // lo*hi
            }
        }
        __syncthreads();
    }
    int nbase = nh * 128;
#pragma unroll
    for (int nt = 0; nt < 16; nt++) {
        int hidx = (nbase >> 1) + nt * 4 + q;
        if (v0) g_h1h[m0 * (HC / 2) + hidx] = __float22half2_rn(make_float2(acc[nt][0], acc[nt][1]));
        if (v1) g_h1h[m1 * (HC / 2) + hidx] = __float22half2_rn(make_float2(acc[nt][2], acc[nt][3]));
    }

    // fused alpha: per-head dot with a_src / a_dst (heads align with nt groups)
    float ps[2][2] = {{0.f, 0.f}, {0.f, 0.f}};
    float pd[2][2] = {{0.f, 0.f}, {0.f, 0.f}};
#pragma unroll
    for (int nt = 0; nt < 16; nt++) {
        int hl = nt >> 3;
        int c0 = nbase + nt * 8 + 2 * q;
        float s0 = a_src[c0], s1 = a_src[c0 + 1];
        float d0 = a_dst[c0], d1 = a_dst[c0 + 1];
        ps[hl][0] += acc[nt][0] * s0 + acc[nt][1] * s1;
        pd[hl][0] += acc[nt][0] * d0 + acc[nt][1] * d1;
        ps[hl][1] += acc[nt][2] * s0 + acc[nt][3] * s1;
        pd[hl][1] += acc[nt][2] * d0 + acc[nt][3] * d1;
    }
#pragma unroll
    for (int off = 1; off <= 2; off <<= 1) {
#pragma unroll
        for (int hl = 0; hl < 2; hl++) {
            ps[hl][0] += __shfl_xor_sync(0xffffffffu, ps[hl][0], off);
            ps[hl][1] += __shfl_xor_sync(0xffffffffu, ps[hl][1], off);
            pd[hl][0] += __shfl_xor_sync(0xffffffffu, pd[hl][0], off);
            pd[hl][1] += __shfl_xor_sync(0xffffffffu, pd[hl][1], off);
        }
    }
    if (q == 0) {
#pragma unroll
        for (int hl = 0; hl < 2; hl++) {
            int gh = nh * 2 + hl;
            if (v0) { g_as1[m0 * 4 + gh] = ps[hl][0]; g_ad1[m0 * 4 + gh] = pd[hl][0]; }
            if (v1) { g_as1[m1 * 4 + gh] = ps[hl][1]; g_ad1[m1 * 4 + gh] = pd[hl][1]; }
        }
    }
}

// ---------------- softmax layer 1: warp per node, no-max, register cache -----
__device__ __forceinline__ float4 e4(float4 a, float4 ad) {
    float4 e;
    e.x = __expf(lrelu(a.x + ad.x, NEG_ATT));
    e.y = __expf(lrelu(a.y + ad.y, NEG_ATT));
    e.z = __expf(lrelu(a.z + ad.z, NEG_ATT));
    e.w = __expf(lrelu(a.w + ad.w, NEG_ATT));
    return e;
}

__global__ __launch_bounds__(256) void k_soft1() {
    int w = threadIdx.x >> 5, lane = threadIdx.x & 31;
    int n = blockIdx.x * 8 + w;
    if (n >= NN) return;
    int base = g_offs[n], deg = g_offs[n + 1] - base;
    float4 ad = ((const float4*)g_ad1)[n];

    float4 ec[4];
    float4 sm = make_float4(0.f, 0.f, 0.f, 0.f);
#pragma unroll
    for (int c = 0; c < 4; c++) {
        int j = lane + c * 32;
        if (j < deg) {
            int s = g_csr[base + j];
            ec[c] = e4(((const float4*)g_as1)[s], ad);
            sm.x += ec[c].x; sm.y += ec[c].y; sm.z += ec[c].z; sm.w += ec[c].w;
        }
    }
    for (int j = lane + 128; j < deg; j += 32) {   // rare deg>128 tail
        int s = g_csr[base + j];
        float4 e = e4(((const float4*)g_as1)[s], ad);
        sm.x += e.x; sm.y += e.y; sm.z += e.z; sm.w += e.w;
    }
#pragma unroll
    for (int off = 16; off > 0; off >>= 1) {
        sm.x += __shfl_xor_sync(0xffffffffu, sm.x, off);
        sm.y += __shfl_xor_sync(0xffffffffu, sm.y, off);
        sm.z += __shfl_xor_sync(0xffffffffu, sm.z, off);
        sm.w += __shfl_xor_sync(0xffffffffu, sm.w, off);
    }
    float4 rv = make_float4(1.f / sm.x, 1.f / sm.y, 1.f / sm.z, 1.f / sm.w);
#pragma unroll
    for (int c = 0; c < 4; c++) {
        int j = lane + c * 32;
        if (j < deg) {
            float4 al = make_float4(ec[c].x * rv.x, ec[c].y * rv.y,
                                    ec[c].z * rv.z, ec[c].w * rv.w);
            ((float4*)g_alE1)[base + j] = al;
        }
    }
    for (int j = lane + 128; j < deg; j += 32) {
        int s = g_csr[base + j];
        float4 e = e4(((const float4*)g_as1)[s], ad);
        ((float4*)g_alE1)[base + j] = make_float4(e.x * rv.x, e.y * rv.y,
                                                  e.z * rv.z, e.w * rv.w);
    }
}

// ---------------- GAT layer 1 aggregation (fp16 gather, half2/thread) --------
__global__ __launch_bounds__(128) void k_gat1(const float* __restrict__ b1) {
    int n = blockIdx.x;
    int t = threadIdx.x;                 // covers channels 2t, 2t+1
    __shared__ int s_src[128];
    __shared__ float s_alpha[128 * 4];
    int base = g_offs[n], deg = g_offs[n + 1] - base;
    int myh = t >> 5;                    // head = (2t)/64
    float ax = 0.f, ay = 0.f;
    for (int cb = 0; cb < deg; cb += 128) {
        int len = min(128, deg - cb);
        if (t < len) {
            s_src[t] = g_csr[base + cb + t];
            *(float4*)&s_alpha[t * 4] = ((const float4*)g_alE1)[base + cb + t];
        }
        __syncthreads();
        int j = 0;
        for (; j + 8 <= len; j += 8) {
            float a0 = s_alpha[(j + 0) * 4 + myh];
            float a1 = s_alpha[(j + 1) * 4 + myh];
            float a2 = s_alpha[(j + 2) * 4 + myh];
            float a3 = s_alpha[(j + 3) * 4 + myh];
            float a4 = s_alpha[(j + 4) * 4 + myh];
            float a5 = s_alpha[(j + 5) * 4 + myh];
            float a6 = s_alpha[(j + 6) * 4 + myh];
            float a7 = s_alpha[(j + 7) * 4 + myh];
            float2 f0 = __half22float2(g_h1h[s_src[j + 0] * (HC / 2) + t]);
            float2 f1 = __half22float2(g_h1h[s_src[j + 1] * (HC / 2) + t]);
            float2 f2 = __half22float2(g_h1h[s_src[j + 2] * (HC / 2) + t]);
            float2 f3 = __half22float2(g_h1h[s_src[j + 3] * (HC / 2) + t]);
            float2 f4 = __half22float2(g_h1h[s_src[j + 4] * (HC / 2) + t]);
            float2 f5 = __half22float2(g_h1h[s_src[j + 5] * (HC / 2) + t]);
            float2 f6 = __half22float2(g_h1h[s_src[j + 6] * (HC / 2) + t]);
            float2 f7 = __half22float2(g_h1h[s_src[j + 7] * (HC / 2) + t]);
            ax = fmaf(a0, f0.x, ax); ay = fmaf(a0, f0.y, ay);
            ax = fmaf(a1, f1.x, ax); ay = fmaf(a1, f1.y, ay);
            ax = fmaf(a2, f2.x, ax); ay = fmaf(a2, f2.y, ay);
            ax = fmaf(a3, f3.x, ax); ay = fmaf(a3, f3.y, ay);
            ax = fmaf(a4, f4.x, ax); ay = fmaf(a4, f4.y, ay);
            ax = fmaf(a5, f5.x, ax); ay = fmaf(a5, f5.y, ay);
            ax = fmaf(a6, f6.x, ax); ay = fmaf(a6, f6.y, ay);
            ax = fmaf(a7, f7.x, ax); ay = fmaf(a7, f7.y, ay);
        }
        for (; j < len; j++) {
            float a = s_alpha[j * 4 + myh];
            float2 f = __half22float2(g_h1h[s_src[j] * (HC / 2) + t]);
            ax = fmaf(a, f.x, ax); ay = fmaf(a, f.y, ay);
        }
        __syncthreads();
    }
    float2 bb = *(const float2*)&b1[2 * t];
    g_agg1h[n * (HC / 2) + t] = __float22half2_rn(make_float2(ax + bb.x, ay + bb.y));
}

// ---------------- BatchNorm: partial sums + fused finalize -------------------
__global__ __launch_bounds__(128) void k_bn(const float* __restrict__ gamma,
                                            const float* __restrict__ beta) {
    int t = threadIdx.x;                 // half2 column t → channels 2t, 2t+1
    int b = blockIdx.x;
    const int NBLK = 256;
    const int RPB = (NN + NBLK - 1) / NBLK;  // 196
    int rs = b * RPB, re = min(NN, rs + RPB);
    float sx = 0.f, sy = 0.f, qx = 0.f, qy = 0.f;
    for (int r = rs; r < re; r++) {
        float2 v = __half22float2(g_agg1h[r * (HC / 2) + t]);
        sx += v.x; sy += v.y;
        qx = fmaf(v.x, v.x, qx); qy = fmaf(v.y, v.y, qy);
    }
    atomicAdd(&g_bnsum[2 * t], sx);
    atomicAdd(&g_bnsum[2 * t + 1], sy);
    atomicAdd(&g_bnsq[2 * t], qx);
    atomicAdd(&g_bnsq[2 * t + 1], qy);
    __threadfence();
    __shared__ int s_last;
    __syncthreads();
    if (t == 0) s_last = (atomicAdd(&g_bncnt, 1) == NBLK - 1);
    __syncthreads();
    if (s_last) {
#pragma unroll
        for (int u = 0; u < 2; u++) {
            int c = 2 * t + u;
            float mean = g_bnsum[c] / (float)NN;
            float var = g_bnsq[c] / (float)NN - mean * mean;
            float rstd = rsqrtf(var + BN_EPS);
            float sc = gamma[c] * rstd;
            g_scale[c] = sc;
            g_shift[c] = beta[c] - mean * sc;
        }
    }
}

// ---------------- GEMM2: fused BN+leaky+split load, fp16 store, alpha2 -------
// grid 391, 256 threads. Warp w: rows [bx*128+w*16, +16), all 64 cols.
__global__ __launch_bounds__(256) void k_gemm2(const float* __restrict__ a_src,
                                               const float* __restrict__ a_dst) {
    __shared__ uint4 bs[8][4][32];     // 16 KB
    __shared__ float s_sc[HC], s_sh[HC];
    int t = threadIdx.x;
    int w = t >> 5, lane = t & 31;
    int g = lane >> 2, q = lane & 3;
    int m0 = blockIdx.x * 128 + w * 16 + g;
    int m1 = m0 + 8;
    bool v0 = m0 < NN, v1 = m1 < NN;
    for (int i = t; i < HC; i += 256) { s_sc[i] = g_scale[i]; s_sh[i] = g_shift[i]; }

    float acc[8][4];
#pragma unroll
    for (int nt = 0; nt < 8; nt++)
#pragma unroll
        for (int r = 0; r < 4; r++) acc[nt][r] = 0.f;

    for (int kq = 0; kq < 4; kq++) {
        const uint4* srcw = g_wf2 + kq * 1024;
        for (int i = t; i < 1024; i += 256) ((uint4*)bs)[i] = srcw[i];
        __syncthreads();
#pragma unroll
        for (int kt = 0; kt < 4; kt++) {
            int kk = kq * 64 + kt * 16 + 2 * q;
            float sc0 = s_sc[kk], sh0 = s_sh[kk];
            float sc1 = s_sc[kk + 1], sh1 = s_sh[kk + 1];
            float sc8 = s_sc[kk + 8], sh8 = s_sh[kk + 8];
            float sc9 = s_sc[kk + 9], sh9 = s_sh[kk + 9];
            uint32_t ah0 = 0, ah1 = 0, ah2 = 0, ah3 = 0;
            uint32_t al0 = 0, al1 = 0, al2 = 0, al3 = 0;
            if (v0) {
                float2 u = __half22float2(g_agg1h[m0 * (HC / 2) + (kk >> 1)]);
                float2 v = __half22float2(g_agg1h[m0 * (HC / 2) + ((kk + 8) >> 1)]);
                u.x = lrelu(fmaf(sc0, u.x, sh0), NEG_ACT);
                u.y = lrelu(fmaf(sc1, u.y, sh1), NEG_ACT);
                v.x = lrelu(fmaf(sc8, v.x, sh8), NEG_ACT);
                v.y = lrelu(fmaf(sc9, v.y, sh9), NEG_ACT);
                split2(u, ah0, al0);
                split2(v, ah2, al2);
            }
            if (v1) {
                float2 u = __half22float2(g_agg1h[m1 * (HC / 2) + (kk >> 1)]);
                float2 v = __half22float2(g_agg1h[m1 * (HC / 2) + ((kk + 8) >> 1)]);
                u.x = lrelu(fmaf(sc0, u.x, sh0), NEG_ACT);
                u.y = lrelu(fmaf(sc1, u.y, sh1), NEG_ACT);
                v.x = lrelu(fmaf(sc8, v.x, sh8), NEG_ACT);
                v.y = lrelu(fmaf(sc9, v.y, sh9), NEG_ACT);
                split2(u, ah1, al1);
                split2(v, ah3, al3);
            }
#pragma unroll
            for (int nt = 0; nt < 8; nt++) {
                uint4 b = bs[nt][kt][lane];
                mma16816(acc[nt], ah0, ah1, ah2, ah3, b.x, b.y);
                mma16816(acc[nt], ah0, ah1, ah2, ah3, b.z, b.w);
                mma16816(acc[nt], al0, al1, al2, al3, b.x, b.y);
            }
        }
        __syncthreads();
    }
#pragma unroll
    for (int nt = 0; nt < 8; nt++) {
        int hidx = nt * 4 + q;
        if (v0) g_h2h[m0 * (C2 / 2) + hidx] = __float22half2_rn(make_float2(acc[nt][0], acc[nt][1]));
        if (v1) g_h2h[m1 * (C2 / 2) + hidx] = __float22half2_rn(make_float2(acc[nt][2], acc[nt][3]));
    }

    // fused alpha2 (single head over all 64 cols)
    float ps0 = 0.f, ps1 = 0.f, pd0 = 0.f, pd1 = 0.f;
#pragma unroll
    for (int nt = 0; nt < 8; nt++) {
        int c0 = nt * 8 + 2 * q;
        float s0 = a_src[c0], s1 = a_src[c0 + 1];
        float d0 = a_dst[c0], d1 = a_dst[c0 + 1];
        ps0 += acc[nt][0] * s0 + acc[nt][1] * s1;
        pd0 += acc[nt][0] * d0 + acc[nt][1] * d1;
        ps1 += acc[nt][2] * s0 + acc[nt][3] * s1;
        pd1 += acc[nt][2] * d0 + acc[nt][3] * d1;
    }
#pragma unroll
    for (int off = 1; off <= 2; off <<= 1) {
        ps0 += __shfl_xor_sync(0xffffffffu, ps0, off);
        ps1 += __shfl_xor_sync(0xffffffffu, ps1, off);
        pd0 += __shfl_xor_sync(0xffffffffu, pd0, off);
        pd1 += __shfl_xor_sync(0xffffffffu, pd1, off);
    }
    if (q == 0) {
        if (v0) { g_as2[m0] = ps0; g_ad2[m0] = pd0; }
        if (v1) { g_as2[m1] = ps1; g_ad2[m1] = pd1; }
    }
}

// ---------------- GAT layer 2: warp/node, no-max softmax, reg cache → out ----
__global__ __launch_bounds__(128) void k_gat2(const float* __restrict__ b2,
                                              float* __restrict__ out) {
    int w = threadIdx.x >> 5, lane = threadIdx.x & 31;
    int n = blockIdx.x * 4 + w;
    if (n >= NN) return;
    int base = g_offs[n], deg = g_offs[n + 1] - base;
    float ad = g_ad2[n];

    int ic[4];
    float en[4];
    float sm = 0.f;
#pragma unroll
    for (int c = 0; c < 4; c++) {
        int j = lane + c * 32;
        ic[c] = 0; en[c] = 0.f;
        if (j < deg) {
            ic[c] = g_csr[base + j];
            en[c] = __expf(lrelu(g_as2[ic[c]] + ad, NEG_ATT));
            sm += en[c];
        }
    }
    for (int j = lane + 128; j < deg; j += 32)     // rare tail
        sm += __expf(lrelu(g_as2[g_csr[base + j]] + ad, NEG_ATT));
#pragma unroll
    for (int off = 16; off > 0; off >>= 1)
        sm += __shfl_xor_sync(0xffffffffu, sm, off);
    float ri = 1.f / sm;

    float ax = 0.f, ay = 0.f;
    for (int cb = 0, c = 0; cb < deg; cb += 32, c++) {
        int len = min(32, deg - cb);
        int myidx;
        float myal;
        if (c < 4) {
            myidx = ic[c];
            myal = en[c] * ri;
        } else {
            myidx = 0; myal = 0.f;
            if (lane < len) {
                myidx = g_csr[base + cb + lane];
                myal = __expf(lrelu(g_as2[myidx] + ad, NEG_ATT)) * ri;
            }
        }
        int j = 0;
        for (; j + 4 <= len; j += 4) {
            int s0 = __shfl_sync(0xffffffffu, myidx, j);
            int s1 = __shfl_sync(0xffffffffu, myidx, j + 1);
            int s2 = __shfl_sync(0xffffffffu, myidx, j + 2);
            int s3 = __shfl_sync(0xffffffffu, myidx, j + 3);
            float a0 = __shfl_sync(0xffffffffu, myal, j);
            float a1 = __shfl_sync(0xffffffffu, myal, j + 1);
            float a2 = __shfl_sync(0xffffffffu, myal, j + 2);
            float a3 = __shfl_sync(0xffffffffu, myal, j + 3);
            float2 f0 = __half22float2(g_h2h[s0 * (C2 / 2) + lane]);
            float2 f1 = __half22float2(g_h2h[s1 * (C2 / 2) + lane]);
            float2 f2 = __half22float2(g_h2h[s2 * (C2 / 2) + lane]);
            float2 f3 = __half22float2(g_h2h[s3 * (C2 / 2) + lane]);
            ax = fmaf(a0, f0.x, ax); ay = fmaf(a0, f0.y, ay);
            ax = fmaf(a1, f1.x, ax); ay = fmaf(a1, f1.y, ay);
            ax = fmaf(a2, f2.x, ax); ay = fmaf(a2, f2.y, ay);
            ax = fmaf(a3, f3.x, ax); ay = fmaf(a3, f3.y, ay);
        }
        for (; j < len; j++) {
            int s = __shfl_sync(0xffffffffu, myidx, j);
            float a = __shfl_sync(0xffffffffu, myal, j);
            float2 f = __half22float2(g_h2h[s * (C2 / 2) + lane]);
            ax = fmaf(a, f.x, ax); ay = fmaf(a, f.y, ay);
        }
    }
    float2 bb = *(const float2*)&b2[2 * lane];
    *(float2*)&out[n * C2 + 2 * lane] = make_float2(ax + bb.x, ay + bb.y);
}

// ---------------- launch -----------------------------------------------------
extern "C" void kernel_launch(void* const* d_in, const int* in_sizes, int n_in,
                              void* d_out, int out_size) {
    const float* x      = (const float*)d_in[0];
    const int*   ei     = (const int*)d_in[1];
    const float* W1     = (const float*)d_in[2];
    const float* a_src1 = (const float*)d_in[3];
    const float* a_dst1 = (const float*)d_in[4];
    const float* b1     = (const float*)d_in[5];
    const float* gamma  = (const float*)d_in[6];
    const float* beta   = (const float*)d_in[7];
    const float* W2     = (const float*)d_in[8];
    const float* a_src2 = (const float*)d_in[9];
    const float* a_dst2 = (const float*)d_in[10];
    const float* b2     = (const float*)d_in[11];
    float* out = (float*)d_out;

    const int* src = ei;
    const int* dst = ei + EE;

    // CSR build
    k_init<<<(NN + 255) / 256, 256>>>();
    k_hist<<<(EE + 255) / 256, 256>>>(dst);
    k_scan_block<<<(NN + 1023) / 1024, 1024>>>();
    k_scan_finish<<<(NN + 255) / 256, 256>>>();
    k_scatter<<<(EE + 255) / 256, 256>>>(src, dst);

    // W fragment prep (both)
    k_prep_w<<<48, 256>>>(W1, W2);

    // Layer 1
    k_gemm1<<<dim3((NN + 127) / 128, 2), 256>>>(x, a_src1, a_dst1);
    k_soft1<<<(NN + 7) / 8, 256>>>();
    k_gat1<<<NN, 128>>>(b1);

    // BatchNorm (partial + fused finalize)
    k_bn<<<256, 128>>>(gamma, beta);

    // Layer 2 (BN+leaky fused into GEMM2 load; softmax fused into gat2)
    k_gemm2<<<(NN + 127) / 128, 256>>>(a_src2, a_dst2);
    k_gat2<<<(NN + 3) / 4, 128>>>(b2, out);
}